// round 2
// baseline (speedup 1.0000x reference)
#include <cuda_runtime.h>

// D-MPNN on GB300. Round 1: fully-fused fp32 scalar baseline.
//
// Pipeline (all default stream, graph-capturable, no allocs):
//   zero(agg0)
//   embed:  x = h @ W_emb                                   [N,128]
//   init :  he = relu([x[src], e] @ W_init + b); scatter agg0[dst] += he
//   for l in 0..3:
//     zero(agg_out)
//     layer:  m = agg_in[src] - he[k^1]
//             he = relu(m @ W_l + b_l) + he; scatter agg_out[dst] += he
//   wrp  :  wrp = W_ro @ W_pred        (readout collapses to per-node dot)
//   outinit: out[b] = b_pred
//   readout: out[gid[n]] += dot(agg_final[n], wrp)

#define NN 200000
#define NE 800000
#define HD 128
#define NGB 2000
#define TILE_E 128
#define SUB_E 16
#define NSUB (TILE_E / SUB_E)

__device__ float g_x[(size_t)NN * HD];          // node embeddings
__device__ float g_he[(size_t)NE * HD];         // edge hidden states (in-place updated)
__device__ float g_agg[2][(size_t)NN * HD];     // ping-pong segment sums
__device__ float g_wrp[HD];                     // W_ro @ W_pred

// ---------------------------------------------------------------- zero agg
__global__ void zero_agg_kernel(int buf) {
    size_t i = (size_t)blockIdx.x * blockDim.x + threadIdx.x;
    size_t n4 = (size_t)NN * HD / 4;
    if (i < n4) reinterpret_cast<float4*>(g_agg[buf])[i] = make_float4(0.f, 0.f, 0.f, 0.f);
}

// ---------------------------------------------------------------- embed: x = h @ W_emb
// 128 threads, 64 nodes per block. W_emb column held in 28 registers.
__global__ void __launch_bounds__(128) embed_kernel(
    const float* __restrict__ h, const float* __restrict__ Wemb)
{
    __shared__ float sh[64 * 28];
    int n0 = blockIdx.x * 64;
    int tid = threadIdx.x;
    for (int idx = tid; idx < 64 * 28; idx += 128)
        sh[idx] = h[(size_t)n0 * 28 + idx];
    __syncthreads();
    float w[28];
#pragma unroll
    for (int i = 0; i < 28; ++i) w[i] = Wemb[i * HD + tid];
    for (int n = 0; n < 64; ++n) {
        float acc = 0.f;
#pragma unroll
        for (int i = 0; i < 28; ++i) acc += sh[n * 28 + i] * w[i];
        g_x[(size_t)(n0 + n) * HD + tid] = acc;
    }
}

// ---------------------------------------------------------------- init message
// he[k] = relu([x[src[k]], e[k]] @ W_init + b_init); agg0[dst[k]] += he[k]
__global__ void __launch_bounds__(256) init_kernel(
    const float* __restrict__ W, const float* __restrict__ bias,
    const float* __restrict__ e, const int* __restrict__ src,
    const int* __restrict__ dst, int outBuf)
{
    extern __shared__ float sm[];
    float* sW = sm;                       // 134*128
    float* sM = sW + 134 * HD;            // 16*128
    float* sB = sM + SUB_E * HD;          // 128
    float* sE = sB + HD;                  // 16*6
    int* sSrc = (int*)(sE + SUB_E * 6);   // 128
    int* sDst = sSrc + TILE_E;            // 128
    float* aggOut = g_agg[outBuf];

    int tid = threadIdx.x;
    int e0 = blockIdx.x * TILE_E;
    for (int i = tid; i < 134 * HD; i += 256) sW[i] = W[i];
    if (tid < HD) sB[tid] = bias[tid];
    if (tid < TILE_E) { sSrc[tid] = src[e0 + tid]; sDst[tid] = dst[e0 + tid]; }
    __syncthreads();

    int tx = tid & 63;   // cols 2*tx, 2*tx+1
    int ty = tid >> 6;   // edges ty, ty+4, ty+8, ty+12

    for (int s = 0; s < NSUB; ++s) {
        int eb = e0 + s * SUB_E;
#pragma unroll
        for (int r = 0; r < SUB_E * HD / 256; ++r) {
            int idx = tid + 256 * r;
            int t = idx >> 7, i = idx & 127;
            sM[idx] = g_x[(size_t)sSrc[s * SUB_E + t] * HD + i];
        }
        if (tid < SUB_E * 6) {
            int t = tid / 6, j = tid % 6;
            sE[tid] = e[(size_t)(eb + t) * 6 + j];
        }
        __syncthreads();

        float acc[4][2];
#pragma unroll
        for (int q = 0; q < 4; ++q) { acc[q][0] = sB[2 * tx]; acc[q][1] = sB[2 * tx + 1]; }
#pragma unroll
        for (int j = 0; j < 6; ++j) {
            float2 w = *(const float2*)&sW[(HD + j) * HD + 2 * tx];
#pragma unroll
            for (int q = 0; q < 4; ++q) {
                float ev = sE[(ty + 4 * q) * 6 + j];
                acc[q][0] += ev * w.x; acc[q][1] += ev * w.y;
            }
        }
#pragma unroll 8
        for (int k = 0; k < HD; ++k) {
            float2 w = *(const float2*)&sW[k * HD + 2 * tx];
#pragma unroll
            for (int q = 0; q < 4; ++q) {
                float m = sM[(ty + 4 * q) * HD + k];
                acc[q][0] += m * w.x; acc[q][1] += m * w.y;
            }
        }
#pragma unroll
        for (int q = 0; q < 4; ++q) {
            int t = ty + 4 * q;
            int ge = eb + t;
            float o0 = fmaxf(acc[q][0], 0.f);
            float o1 = fmaxf(acc[q][1], 0.f);
            *(float2*)&g_he[(size_t)ge * HD + 2 * tx] = make_float2(o0, o1);
            int dv = sDst[s * SUB_E + t];
            atomicAdd(&aggOut[(size_t)dv * HD + 2 * tx], o0);
            atomicAdd(&aggOut[(size_t)dv * HD + 2 * tx + 1], o1);
        }
        __syncthreads();
    }
}

// ---------------------------------------------------------------- D-MPNN layer
// m = agg_in[src[k]] - he[k^1]; he[k] = relu(m @ W + b) + he[k]; agg_out[dst[k]] += he[k]
// Pairs (2i, 2i+1) live in the same 16-edge sub-tile, so in-place he update is safe.
__global__ void __launch_bounds__(256) layer_kernel(
    const float* __restrict__ W, const float* __restrict__ bias,
    const int* __restrict__ src, const int* __restrict__ dst,
    int inBuf, int outBuf)
{
    extern __shared__ float sm[];
    float* sW = sm;                       // 128*128
    float* sM = sW + HD * HD;             // 16*128
    float* sB = sM + SUB_E * HD;          // 128
    int* sSrc = (int*)(sB + HD);          // 128
    int* sDst = sSrc + TILE_E;            // 128
    const float* aggIn = g_agg[inBuf];
    float* aggOut = g_agg[outBuf];

    int tid = threadIdx.x;
    int e0 = blockIdx.x * TILE_E;
    for (int i = tid; i < HD * HD; i += 256) sW[i] = W[i];
    if (tid < HD) sB[tid] = bias[tid];
    if (tid < TILE_E) { sSrc[tid] = src[e0 + tid]; sDst[tid] = dst[e0 + tid]; }
    __syncthreads();

    int tx = tid & 63;
    int ty = tid >> 6;

    for (int s = 0; s < NSUB; ++s) {
        int eb = e0 + s * SUB_E;
#pragma unroll
        for (int r = 0; r < SUB_E * HD / 256; ++r) {
            int idx = tid + 256 * r;
            int t = idx >> 7, i = idx & 127;
            sM[idx] = aggIn[(size_t)sSrc[s * SUB_E + t] * HD + i]
                    - g_he[(size_t)(eb + (t ^ 1)) * HD + i];
        }
        __syncthreads();

        float acc[4][2];
#pragma unroll
        for (int q = 0; q < 4; ++q) { acc[q][0] = 0.f; acc[q][1] = 0.f; }
#pragma unroll 8
        for (int k = 0; k < HD; ++k) {
            float2 w = *(const float2*)&sW[k * HD + 2 * tx];
#pragma unroll
            for (int q = 0; q < 4; ++q) {
                float m = sM[(ty + 4 * q) * HD + k];
                acc[q][0] += m * w.x; acc[q][1] += m * w.y;
            }
        }
        float b0 = sB[2 * tx], b1 = sB[2 * tx + 1];
#pragma unroll
        for (int q = 0; q < 4; ++q) {
            int t = ty + 4 * q;
            int ge = eb + t;
            float2 hv = *(const float2*)&g_he[(size_t)ge * HD + 2 * tx];
            float o0 = fmaxf(acc[q][0] + b0, 0.f) + hv.x;
            float o1 = fmaxf(acc[q][1] + b1, 0.f) + hv.y;
            *(float2*)&g_he[(size_t)ge * HD + 2 * tx] = make_float2(o0, o1);
            int dv = sDst[s * SUB_E + t];
            atomicAdd(&aggOut[(size_t)dv * HD + 2 * tx], o0);
            atomicAdd(&aggOut[(size_t)dv * HD + 2 * tx + 1], o1);
        }
        __syncthreads();
    }
}

// ---------------------------------------------------------------- wrp = W_ro @ W_pred
__global__ void wrp_kernel(const float* __restrict__ Wro, const float* __restrict__ Wpred) {
    __shared__ float sp[HD];
    int i = threadIdx.x;
    sp[i] = Wpred[i];
    __syncthreads();
    float a = 0.f;
    for (int j = 0; j < HD; ++j) a += Wro[(size_t)i * HD + j] * sp[j];
    g_wrp[i] = a;
}

// ---------------------------------------------------------------- out[b] = b_pred
__global__ void outinit_kernel(float* __restrict__ out, const float* __restrict__ bpred) {
    int i = blockIdx.x * blockDim.x + threadIdx.x;
    if (i < NGB) out[i] = bpred[0];
}

// ---------------------------------------------------------------- readout
// out[gid[n]] += dot(agg_final[n], wrp).  One warp per node.
__global__ void __launch_bounds__(256) readout_kernel(
    const int* __restrict__ gid, float* __restrict__ out, int buf)
{
    int node = (blockIdx.x * blockDim.x + threadIdx.x) >> 5;
    int lane = threadIdx.x & 31;
    if (node >= NN) return;
    const float4 v = reinterpret_cast<const float4*>(&g_agg[buf][(size_t)node * HD])[lane];
    const float4 w = reinterpret_cast<const float4*>(g_wrp)[lane];
    float s = v.x * w.x + v.y * w.y + v.z * w.z + v.w * w.w;
#pragma unroll
    for (int o = 16; o; o >>= 1) s += __shfl_xor_sync(0xFFFFFFFFu, s, o);
    if (lane == 0) atomicAdd(&out[gid[node]], s);
}

// ---------------------------------------------------------------- launch
static const int INIT_SMEM  = (134 * HD + SUB_E * HD + HD + SUB_E * 6) * 4 + 2 * TILE_E * 4;
static const int LAYER_SMEM = (HD * HD + SUB_E * HD + HD) * 4 + 2 * TILE_E * 4;

extern "C" void kernel_launch(void* const* d_in, const int* in_sizes, int n_in,
                              void* d_out, int out_size)
{
    const float* h      = (const float*)d_in[0];
    const float* e      = (const float*)d_in[1];
    const float* Wemb   = (const float*)d_in[2];
    const float* Winit  = (const float*)d_in[3];
    const float* binit  = (const float*)d_in[4];
    const float* Wlay   = (const float*)d_in[5];
    const float* blay   = (const float*)d_in[6];
    const float* Wro    = (const float*)d_in[7];
    const float* Wpred  = (const float*)d_in[8];
    const float* bpred  = (const float*)d_in[9];
    const int*   src    = (const int*)d_in[10];
    const int*   dst    = (const int*)d_in[11];
    const int*   gid    = (const int*)d_in[12];
    float* out = (float*)d_out;

    cudaFuncSetAttribute(init_kernel,  cudaFuncAttributeMaxDynamicSharedMemorySize, INIT_SMEM);
    cudaFuncSetAttribute(layer_kernel, cudaFuncAttributeMaxDynamicSharedMemorySize, LAYER_SMEM);

    const int zeroBlocks  = (int)(((size_t)NN * HD / 4 + 255) / 256);
    const int edgeBlocks  = NE / TILE_E;   // 6250
    const int embedBlocks = NN / 64;       // 3125

    zero_agg_kernel<<<zeroBlocks, 256>>>(0);
    embed_kernel<<<embedBlocks, 128>>>(h, Wemb);
    init_kernel<<<edgeBlocks, 256, INIT_SMEM>>>(Winit, binit, e, src, dst, 0);

    for (int l = 0; l < 4; ++l) {
        int inBuf  = l & 1;
        int outBuf = 1 - inBuf;
        zero_agg_kernel<<<zeroBlocks, 256>>>(outBuf);
        layer_kernel<<<edgeBlocks, 256, LAYER_SMEM>>>(
            Wlay + (size_t)l * HD * HD, blay + (size_t)l * HD, src, dst, inBuf, outBuf);
    }

    wrp_kernel<<<1, HD>>>(Wro, Wpred);
    outinit_kernel<<<(NGB + 255) / 256, 256>>>(out, bpred);
    readout_kernel<<<(NN * 32 + 255) / 256, 256>>>(gid, out, 0);  // final agg is buffer 0
}

// round 4
// speedup vs baseline: 1.0638x; 1.0638x over previous
#include <cuda_runtime.h>
#include <cuda_bf16.h>
#include <mma.h>

using namespace nvcuda;

// D-MPNN on GB300. Round 4: R2 tensor-core design with the scatter-offset
// bug fixed (aggPtr + 4*c, not 16*c).

#define NN 200000
#define NE 800000
#define HD 128
#define NGB 2000
#define TE 256              // edges per block (NE/TE = 3125 exactly)
#define NTHR 512
#define LDA 136             // bf16 smem leading dim
#define LDS_F 132           // fp32 staging leading dim

__device__ float g_x[(size_t)NN * HD];
__device__ float g_he[(size_t)NE * HD];
__device__ float g_agg[2][(size_t)NN * HD];
__device__ float g_wrp[HD];

// smem byte offsets
#define OFF_AHI   0
#define OFF_ALO   (OFF_AHI + TE * LDA * 2)
#define OFF_WHI   (OFF_ALO + TE * LDA * 2)
#define OFF_WLO   (OFF_WHI + HD * LDA * 2)
#define OFF_B     (OFF_WLO + HD * LDA * 2)
#define OFF_W2    (OFF_B + HD * 4)
#define OFF_E     (OFF_W2 + 6 * HD * 4)
#define OFF_SRC_L (OFF_B + HD * 4)
#define OFF_SRC_I (OFF_E + TE * 6 * 4)
#define SMEM_LAYER (OFF_SRC_L + 2 * TE * 4)
#define SMEM_INIT  (OFF_SRC_I + 2 * TE * 4)

__device__ __forceinline__ void red_add_v4(float* ptr, float4 v) {
    asm volatile("red.global.add.v4.f32 [%0], {%1, %2, %3, %4};"
                 :: "l"(ptr), "f"(v.x), "f"(v.y), "f"(v.z), "f"(v.w) : "memory");
}

__device__ __forceinline__ void split_store(__nv_bfloat16* hi, __nv_bfloat16* lo, float v) {
    __nv_bfloat16 h = __float2bfloat16_rn(v);
    *hi = h;
    *lo = __float2bfloat16_rn(v - __bfloat162float(h));
}

// ---------------------------------------------------------------- zero agg
__global__ void zero_agg_kernel(int buf) {
    size_t i = (size_t)blockIdx.x * blockDim.x + threadIdx.x;
    size_t n4 = (size_t)NN * HD / 4;
    if (i < n4) reinterpret_cast<float4*>(g_agg[buf])[i] = make_float4(0.f, 0.f, 0.f, 0.f);
}

// ---------------------------------------------------------------- embed: x = h @ W_emb
__global__ void __launch_bounds__(128) embed_kernel(
    const float* __restrict__ h, const float* __restrict__ Wemb)
{
    __shared__ float sh[64 * 28];
    int n0 = blockIdx.x * 64;
    int tid = threadIdx.x;
    for (int idx = tid; idx < 64 * 28; idx += 128)
        sh[idx] = h[(size_t)n0 * 28 + idx];
    __syncthreads();
    float w[28];
#pragma unroll
    for (int i = 0; i < 28; ++i) w[i] = Wemb[i * HD + tid];
    for (int n = 0; n < 64; ++n) {
        float acc = 0.f;
#pragma unroll
        for (int i = 0; i < 28; ++i) acc += sh[n * 28 + i] * w[i];
        g_x[(size_t)(n0 + n) * HD + tid] = acc;
    }
}

// ---------------------------------------------------------------- shared MMA core
// stag[TE][128] = sA @ sW (hi/lo split, fp32 accum), staged to smem (aliases sA).
__device__ __forceinline__ void mma_core(char* sm) {
    const __nv_bfloat16* sAhi = (const __nv_bfloat16*)(sm + OFF_AHI);
    const __nv_bfloat16* sAlo = (const __nv_bfloat16*)(sm + OFF_ALO);
    const __nv_bfloat16* sWhi = (const __nv_bfloat16*)(sm + OFF_WHI);
    const __nv_bfloat16* sWlo = (const __nv_bfloat16*)(sm + OFF_WLO);
    float* stag = (float*)(sm + OFF_AHI);

    int w = threadIdx.x >> 5;
    int mrow = (w >> 1) * 32;
    int ncol = (w & 1) * 64;

    wmma::fragment<wmma::accumulator, 16, 16, 16, float> acc[2][4];
#pragma unroll
    for (int i = 0; i < 2; ++i)
#pragma unroll
        for (int n = 0; n < 4; ++n) wmma::fill_fragment(acc[i][n], 0.f);

#pragma unroll
    for (int kt = 0; kt < 8; ++kt) {
        wmma::fragment<wmma::matrix_a, 16, 16, 16, __nv_bfloat16, wmma::row_major> ahi[2], alo[2];
#pragma unroll
        for (int i = 0; i < 2; ++i) {
            wmma::load_matrix_sync(ahi[i], sAhi + (mrow + 16 * i) * LDA + kt * 16, LDA);
            wmma::load_matrix_sync(alo[i], sAlo + (mrow + 16 * i) * LDA + kt * 16, LDA);
        }
#pragma unroll
        for (int nt = 0; nt < 4; ++nt) {
            wmma::fragment<wmma::matrix_b, 16, 16, 16, __nv_bfloat16, wmma::row_major> bhi, blo;
            wmma::load_matrix_sync(bhi, sWhi + (kt * 16) * LDA + ncol + nt * 16, LDA);
            wmma::load_matrix_sync(blo, sWlo + (kt * 16) * LDA + ncol + nt * 16, LDA);
#pragma unroll
            for (int i = 0; i < 2; ++i) {
                wmma::mma_sync(acc[i][nt], ahi[i], bhi, acc[i][nt]);
                wmma::mma_sync(acc[i][nt], alo[i], bhi, acc[i][nt]);
                wmma::mma_sync(acc[i][nt], ahi[i], blo, acc[i][nt]);
            }
        }
    }
    __syncthreads();
#pragma unroll
    for (int i = 0; i < 2; ++i)
#pragma unroll
        for (int nt = 0; nt < 4; ++nt)
            wmma::store_matrix_sync(stag + (mrow + 16 * i) * LDS_F + ncol + nt * 16,
                                    acc[i][nt], LDS_F, wmma::mem_row_major);
    __syncthreads();
}

__device__ __forceinline__ void load_W_split(char* sm, const float* __restrict__ W) {
    __nv_bfloat16* sWhi = (__nv_bfloat16*)(sm + OFF_WHI);
    __nv_bfloat16* sWlo = (__nv_bfloat16*)(sm + OFF_WLO);
    for (int i = threadIdx.x; i < HD * HD; i += NTHR) {
        int k = i >> 7, n = i & 127;
        split_store(&sWhi[k * LDA + n], &sWlo[k * LDA + n], W[i]);
    }
}

// ---------------------------------------------------------------- init message
__global__ void __launch_bounds__(NTHR) init_kernel(
    const float* __restrict__ W, const float* __restrict__ bias,
    const float* __restrict__ e, const int* __restrict__ src,
    const int* __restrict__ dst, int outBuf)
{
    extern __shared__ char sm[];
    __nv_bfloat16* sAhi = (__nv_bfloat16*)(sm + OFF_AHI);
    __nv_bfloat16* sAlo = (__nv_bfloat16*)(sm + OFF_ALO);
    float* sB = (float*)(sm + OFF_B);
    float* sW2 = (float*)(sm + OFF_W2);
    float* sE = (float*)(sm + OFF_E);
    int* sSrc = (int*)(sm + OFF_SRC_I);
    int* sDst = sSrc + TE;
    float* stag = (float*)(sm + OFF_AHI);
    float* aggOut = g_agg[outBuf];

    int tid = threadIdx.x;
    int e0 = blockIdx.x * TE;

    load_W_split(sm, W);
    for (int i = tid; i < 6 * HD; i += NTHR) sW2[i] = W[HD * HD + i];
    if (tid < HD) sB[tid] = bias[tid];
    if (tid < TE) { sSrc[tid] = src[e0 + tid]; sDst[tid] = dst[e0 + tid]; }
    for (int i = tid; i < TE * 6; i += NTHR) sE[i] = e[(size_t)e0 * 6 + i];
    __syncthreads();

    int r = tid >> 1, ch = (tid & 1) * 64;
    {
        const float4* a = (const float4*)&g_x[(size_t)sSrc[r] * HD + ch];
        __nv_bfloat16* dh = &sAhi[r * LDA + ch];
        __nv_bfloat16* dl = &sAlo[r * LDA + ch];
#pragma unroll
        for (int c = 0; c < 16; ++c) {
            float4 v = a[c];
            split_store(dh + 4 * c + 0, dl + 4 * c + 0, v.x);
            split_store(dh + 4 * c + 1, dl + 4 * c + 1, v.y);
            split_store(dh + 4 * c + 2, dl + 4 * c + 2, v.z);
            split_store(dh + 4 * c + 3, dl + 4 * c + 3, v.w);
        }
    }
    __syncthreads();

    mma_core(sm);

    float ev[6];
#pragma unroll
    for (int j = 0; j < 6; ++j) ev[j] = sE[r * 6 + j];
    float4* hePtr = (float4*)&g_he[(size_t)(e0 + r) * HD + ch];
    float* aggPtr = &aggOut[(size_t)sDst[r] * HD + ch];
    const float* stRow = &stag[r * LDS_F + ch];
#pragma unroll 4
    for (int c = 0; c < 16; ++c) {
        float4 st = *(const float4*)(stRow + 4 * c);
        float4 b  = *(const float4*)&sB[ch + 4 * c];
        float4 o;
        o.x = st.x + b.x; o.y = st.y + b.y; o.z = st.z + b.z; o.w = st.w + b.w;
#pragma unroll
        for (int j = 0; j < 6; ++j) {
            float4 w2 = *(const float4*)&sW2[j * HD + ch + 4 * c];
            o.x += ev[j] * w2.x; o.y += ev[j] * w2.y; o.z += ev[j] * w2.z; o.w += ev[j] * w2.w;
        }
        o.x = fmaxf(o.x, 0.f); o.y = fmaxf(o.y, 0.f); o.z = fmaxf(o.z, 0.f); o.w = fmaxf(o.w, 0.f);
        hePtr[c] = o;
        red_add_v4(aggPtr + 4 * c, o);   // FIXED: was + 16*c
    }
}

// ---------------------------------------------------------------- D-MPNN layer
__global__ void __launch_bounds__(NTHR) layer_kernel(
    const float* __restrict__ W, const float* __restrict__ bias,
    const int* __restrict__ src, const int* __restrict__ dst,
    int inBuf, int outBuf)
{
    extern __shared__ char sm[];
    __nv_bfloat16* sAhi = (__nv_bfloat16*)(sm + OFF_AHI);
    __nv_bfloat16* sAlo = (__nv_bfloat16*)(sm + OFF_ALO);
    float* sB = (float*)(sm + OFF_B);
    int* sSrc = (int*)(sm + OFF_SRC_L);
    int* sDst = sSrc + TE;
    float* stag = (float*)(sm + OFF_AHI);
    const float* aggIn = g_agg[inBuf];
    float* aggOut = g_agg[outBuf];

    int tid = threadIdx.x;
    int e0 = blockIdx.x * TE;

    load_W_split(sm, W);
    if (tid < HD) sB[tid] = bias[tid];
    if (tid < TE) { sSrc[tid] = src[e0 + tid]; sDst[tid] = dst[e0 + tid]; }
    __syncthreads();

    int r = tid >> 1, ch = (tid & 1) * 64;
    {
        const float4* a = (const float4*)&aggIn[(size_t)sSrc[r] * HD + ch];
        const float4* hr = (const float4*)&g_he[(size_t)(e0 + (r ^ 1)) * HD + ch];
        __nv_bfloat16* dh = &sAhi[r * LDA + ch];
        __nv_bfloat16* dl = &sAlo[r * LDA + ch];
#pragma unroll
        for (int c = 0; c < 16; ++c) {
            float4 av = a[c]; float4 hv = hr[c];
            split_store(dh + 4 * c + 0, dl + 4 * c + 0, av.x - hv.x);
            split_store(dh + 4 * c + 1, dl + 4 * c + 1, av.y - hv.y);
            split_store(dh + 4 * c + 2, dl + 4 * c + 2, av.z - hv.z);
            split_store(dh + 4 * c + 3, dl + 4 * c + 3, av.w - hv.w);
        }
    }
    __syncthreads();

    mma_core(sm);

    float4* hePtr = (float4*)&g_he[(size_t)(e0 + r) * HD + ch];
    float* aggPtr = &aggOut[(size_t)sDst[r] * HD + ch];
    const float* stRow = &stag[r * LDS_F + ch];
#pragma unroll 4
    for (int c = 0; c < 16; ++c) {
        float4 st = *(const float4*)(stRow + 4 * c);
        float4 b  = *(const float4*)&sB[ch + 4 * c];
        float4 hv = hePtr[c];
        float4 o;
        o.x = fmaxf(st.x + b.x, 0.f) + hv.x;
        o.y = fmaxf(st.y + b.y, 0.f) + hv.y;
        o.z = fmaxf(st.z + b.z, 0.f) + hv.z;
        o.w = fmaxf(st.w + b.w, 0.f) + hv.w;
        hePtr[c] = o;
        red_add_v4(aggPtr + 4 * c, o);   // FIXED: was + 16*c
    }
}

// ---------------------------------------------------------------- wrp = W_ro @ W_pred
__global__ void wrp_kernel(const float* __restrict__ Wro, const float* __restrict__ Wpred) {
    __shared__ float sp[HD];
    int i = threadIdx.x;
    sp[i] = Wpred[i];
    __syncthreads();
    float a = 0.f;
    for (int j = 0; j < HD; ++j) a += Wro[(size_t)i * HD + j] * sp[j];
    g_wrp[i] = a;
}

__global__ void outinit_kernel(float* __restrict__ out, const float* __restrict__ bpred) {
    int i = blockIdx.x * blockDim.x + threadIdx.x;
    if (i < NGB) out[i] = bpred[0];
}

// ---------------------------------------------------------------- readout
__global__ void __launch_bounds__(256) readout_kernel(
    const int* __restrict__ gid, float* __restrict__ out, int buf)
{
    int node = (blockIdx.x * blockDim.x + threadIdx.x) >> 5;
    int lane = threadIdx.x & 31;
    if (node >= NN) return;
    const float4 v = reinterpret_cast<const float4*>(&g_agg[buf][(size_t)node * HD])[lane];
    const float4 w = reinterpret_cast<const float4*>(g_wrp)[lane];
    float s = v.x * w.x + v.y * w.y + v.z * w.z + v.w * w.w;
#pragma unroll
    for (int o = 16; o; o >>= 1) s += __shfl_xor_sync(0xFFFFFFFFu, s, o);
    if (lane == 0) atomicAdd(&out[gid[node]], s);
}

// ---------------------------------------------------------------- launch
extern "C" void kernel_launch(void* const* d_in, const int* in_sizes, int n_in,
                              void* d_out, int out_size)
{
    const float* h      = (const float*)d_in[0];
    const float* e      = (const float*)d_in[1];
    const float* Wemb   = (const float*)d_in[2];
    const float* Winit  = (const float*)d_in[3];
    const float* binit  = (const float*)d_in[4];
    const float* Wlay   = (const float*)d_in[5];
    const float* blay   = (const float*)d_in[6];
    const float* Wro    = (const float*)d_in[7];
    const float* Wpred  = (const float*)d_in[8];
    const float* bpred  = (const float*)d_in[9];
    const int*   src    = (const int*)d_in[10];
    const int*   dst    = (const int*)d_in[11];
    const int*   gid    = (const int*)d_in[12];
    float* out = (float*)d_out;

    cudaFuncSetAttribute(init_kernel,  cudaFuncAttributeMaxDynamicSharedMemorySize, SMEM_INIT);
    cudaFuncSetAttribute(layer_kernel, cudaFuncAttributeMaxDynamicSharedMemorySize, SMEM_LAYER);

    const int zeroBlocks = (int)(((size_t)NN * HD / 4 + 255) / 256);
    const int edgeBlocks = NE / TE;
    const int embedBlocks = NN / 64;

    zero_agg_kernel<<<zeroBlocks, 256>>>(0);
    embed_kernel<<<embedBlocks, 128>>>(h, Wemb);
    init_kernel<<<edgeBlocks, NTHR, SMEM_INIT>>>(Winit, binit, e, src, dst, 0);

    for (int l = 0; l < 4; ++l) {
        int inBuf = l & 1;
        int outBuf = 1 - inBuf;
        zero_agg_kernel<<<zeroBlocks, 256>>>(outBuf);
        layer_kernel<<<edgeBlocks, NTHR, SMEM_LAYER>>>(
            Wlay + (size_t)l * HD * HD, blay + (size_t)l * HD, src, dst, inBuf, outBuf);
    }

    wrp_kernel<<<1, HD>>>(Wro, Wpred);
    outinit_kernel<<<(NGB + 255) / 256, 256>>>(out, bpred);
    readout_kernel<<<(NN * 32 + 255) / 256, 256>>>(gid, out, 0);
}

// round 5
// speedup vs baseline: 1.1812x; 1.1104x over previous
#include <cuda_runtime.h>
#include <cuda_bf16.h>
#include <mma.h>

using namespace nvcuda;

// D-MPNN on GB300. Round 5: CSR-gather aggregation (no atomics, no zero pass),
// GEMM kernels unchanged from R4 minus the scatter. Launch order puts
// init_kernel at ncu's captured index (5).

#define NN 200000
#define NE 800000
#define HD 128
#define NGB 2000
#define TE 256
#define NTHR 512
#define LDA 136
#define LDS_F 132
#define SCANB 512
#define NSCAN ((NN + SCANB - 1) / SCANB)   // 391

__device__ float g_x[(size_t)NN * HD];
__device__ float g_he[(size_t)NE * HD];
__device__ float g_agg[(size_t)NN * HD];
__device__ float g_wrp[HD];
__device__ int g_deg[NN];
__device__ int g_off[NN];
__device__ int g_cursor[NN];
__device__ int g_csr[NE];
__device__ int g_bsum[NSCAN];

// smem byte offsets (GEMM kernels)
#define OFF_AHI   0
#define OFF_ALO   (OFF_AHI + TE * LDA * 2)
#define OFF_WHI   (OFF_ALO + TE * LDA * 2)
#define OFF_WLO   (OFF_WHI + HD * LDA * 2)
#define OFF_B     (OFF_WLO + HD * LDA * 2)
#define OFF_W2    (OFF_B + HD * 4)
#define OFF_E     (OFF_W2 + 6 * HD * 4)
#define OFF_SRC_L (OFF_B + HD * 4)
#define OFF_SRC_I (OFF_E + TE * 6 * 4)
#define SMEM_GEMM (OFF_SRC_L + TE * 4)
#define SMEM_INIT (OFF_SRC_I + TE * 4)

__device__ __forceinline__ void split_store(__nv_bfloat16* hi, __nv_bfloat16* lo, float v) {
    __nv_bfloat16 h = __float2bfloat16_rn(v);
    *hi = h;
    *lo = __float2bfloat16_rn(v - __bfloat162float(h));
}

// ---------------------------------------------------------------- CSR build
__global__ void zero_deg_kernel() {
    int i = blockIdx.x * blockDim.x + threadIdx.x;
    if (i < NN) g_deg[i] = 0;
}

__global__ void deg_count_kernel(const int* __restrict__ dst) {
    int k = blockIdx.x * blockDim.x + threadIdx.x;
    if (k < NE) atomicAdd(&g_deg[dst[k]], 1);
}

__global__ void scan_a_kernel() {   // block sums of deg
    __shared__ int s[SCANB];
    int t = threadIdx.x;
    int n = blockIdx.x * SCANB + t;
    s[t] = (n < NN) ? g_deg[n] : 0;
    __syncthreads();
    for (int o = SCANB / 2; o > 0; o >>= 1) {
        if (t < o) s[t] += s[t + o];
        __syncthreads();
    }
    if (t == 0) g_bsum[blockIdx.x] = s[0];
}

__global__ void scan_b_kernel() {   // serial prefix over block sums
    if (threadIdx.x == 0) {
        int run = 0;
        for (int b = 0; b < NSCAN; ++b) { int v = g_bsum[b]; g_bsum[b] = run; run += v; }
    }
}

__global__ void scan_c_kernel() {   // per-block exclusive scan -> offsets, cursor
    __shared__ int s[SCANB];
    int t = threadIdx.x;
    int n = blockIdx.x * SCANB + t;
    int val = (n < NN) ? g_deg[n] : 0;
    s[t] = val;
    __syncthreads();
    for (int o = 1; o < SCANB; o <<= 1) {
        int x = (t >= o) ? s[t - o] : 0;
        __syncthreads();
        s[t] += x;
        __syncthreads();
    }
    if (n < NN) {
        int off = g_bsum[blockIdx.x] + s[t] - val;
        g_off[n] = off;
        g_cursor[n] = off;
    }
}

__global__ void csr_fill_kernel(const int* __restrict__ dst) {
    int k = blockIdx.x * blockDim.x + threadIdx.x;
    if (k < NE) {
        int pos = atomicAdd(&g_cursor[dst[k]], 1);
        g_csr[pos] = k;
    }
}

// ---------------------------------------------------------------- embed
__global__ void __launch_bounds__(128) embed_kernel(
    const float* __restrict__ h, const float* __restrict__ Wemb)
{
    __shared__ float sh[64 * 28];
    int n0 = blockIdx.x * 64;
    int tid = threadIdx.x;
    for (int idx = tid; idx < 64 * 28; idx += 128)
        sh[idx] = h[(size_t)n0 * 28 + idx];
    __syncthreads();
    float w[28];
#pragma unroll
    for (int i = 0; i < 28; ++i) w[i] = Wemb[i * HD + tid];
    for (int n = 0; n < 64; ++n) {
        float acc = 0.f;
#pragma unroll
        for (int i = 0; i < 28; ++i) acc += sh[n * 28 + i] * w[i];
        g_x[(size_t)(n0 + n) * HD + tid] = acc;
    }
}

// ---------------------------------------------------------------- MMA core
__device__ __forceinline__ void mma_core(char* sm) {
    const __nv_bfloat16* sAhi = (const __nv_bfloat16*)(sm + OFF_AHI);
    const __nv_bfloat16* sAlo = (const __nv_bfloat16*)(sm + OFF_ALO);
    const __nv_bfloat16* sWhi = (const __nv_bfloat16*)(sm + OFF_WHI);
    const __nv_bfloat16* sWlo = (const __nv_bfloat16*)(sm + OFF_WLO);
    float* stag = (float*)(sm + OFF_AHI);

    int w = threadIdx.x >> 5;
    int mrow = (w >> 1) * 32;
    int ncol = (w & 1) * 64;

    wmma::fragment<wmma::accumulator, 16, 16, 16, float> acc[2][4];
#pragma unroll
    for (int i = 0; i < 2; ++i)
#pragma unroll
        for (int n = 0; n < 4; ++n) wmma::fill_fragment(acc[i][n], 0.f);

#pragma unroll
    for (int kt = 0; kt < 8; ++kt) {
        wmma::fragment<wmma::matrix_a, 16, 16, 16, __nv_bfloat16, wmma::row_major> ahi[2], alo[2];
#pragma unroll
        for (int i = 0; i < 2; ++i) {
            wmma::load_matrix_sync(ahi[i], sAhi + (mrow + 16 * i) * LDA + kt * 16, LDA);
            wmma::load_matrix_sync(alo[i], sAlo + (mrow + 16 * i) * LDA + kt * 16, LDA);
        }
#pragma unroll
        for (int nt = 0; nt < 4; ++nt) {
            wmma::fragment<wmma::matrix_b, 16, 16, 16, __nv_bfloat16, wmma::row_major> bhi, blo;
            wmma::load_matrix_sync(bhi, sWhi + (kt * 16) * LDA + ncol + nt * 16, LDA);
            wmma::load_matrix_sync(blo, sWlo + (kt * 16) * LDA + ncol + nt * 16, LDA);
#pragma unroll
            for (int i = 0; i < 2; ++i) {
                wmma::mma_sync(acc[i][nt], ahi[i], bhi, acc[i][nt]);
                wmma::mma_sync(acc[i][nt], alo[i], bhi, acc[i][nt]);
                wmma::mma_sync(acc[i][nt], ahi[i], blo, acc[i][nt]);
            }
        }
    }
    __syncthreads();
#pragma unroll
    for (int i = 0; i < 2; ++i)
#pragma unroll
        for (int nt = 0; nt < 4; ++nt)
            wmma::store_matrix_sync(stag + (mrow + 16 * i) * LDS_F + ncol + nt * 16,
                                    acc[i][nt], LDS_F, wmma::mem_row_major);
    __syncthreads();
}

__device__ __forceinline__ void load_W_split(char* sm, const float* __restrict__ W) {
    __nv_bfloat16* sWhi = (__nv_bfloat16*)(sm + OFF_WHI);
    __nv_bfloat16* sWlo = (__nv_bfloat16*)(sm + OFF_WLO);
    for (int i = threadIdx.x; i < HD * HD; i += NTHR) {
        int k = i >> 7, n = i & 127;
        split_store(&sWhi[k * LDA + n], &sWlo[k * LDA + n], W[i]);
    }
}

// ---------------------------------------------------------------- init (GEMM, no scatter)
__global__ void __launch_bounds__(NTHR) init_kernel(
    const float* __restrict__ W, const float* __restrict__ bias,
    const float* __restrict__ e, const int* __restrict__ src)
{
    extern __shared__ char sm[];
    __nv_bfloat16* sAhi = (__nv_bfloat16*)(sm + OFF_AHI);
    __nv_bfloat16* sAlo = (__nv_bfloat16*)(sm + OFF_ALO);
    float* sB = (float*)(sm + OFF_B);
    float* sW2 = (float*)(sm + OFF_W2);
    float* sE = (float*)(sm + OFF_E);
    int* sSrc = (int*)(sm + OFF_SRC_I);
    float* stag = (float*)(sm + OFF_AHI);

    int tid = threadIdx.x;
    int e0 = blockIdx.x * TE;

    load_W_split(sm, W);
    for (int i = tid; i < 6 * HD; i += NTHR) sW2[i] = W[HD * HD + i];
    if (tid < HD) sB[tid] = bias[tid];
    if (tid < TE) sSrc[tid] = src[e0 + tid];
    for (int i = tid; i < TE * 6; i += NTHR) sE[i] = e[(size_t)e0 * 6 + i];
    __syncthreads();

    int r = tid >> 1, ch = (tid & 1) * 64;
    {
        const float4* a = (const float4*)&g_x[(size_t)sSrc[r] * HD + ch];
        __nv_bfloat16* dh = &sAhi[r * LDA + ch];
        __nv_bfloat16* dl = &sAlo[r * LDA + ch];
#pragma unroll
        for (int c = 0; c < 16; ++c) {
            float4 v = a[c];
            split_store(dh + 4 * c + 0, dl + 4 * c + 0, v.x);
            split_store(dh + 4 * c + 1, dl + 4 * c + 1, v.y);
            split_store(dh + 4 * c + 2, dl + 4 * c + 2, v.z);
            split_store(dh + 4 * c + 3, dl + 4 * c + 3, v.w);
        }
    }
    __syncthreads();

    mma_core(sm);

    float ev[6];
#pragma unroll
    for (int j = 0; j < 6; ++j) ev[j] = sE[r * 6 + j];
    float4* hePtr = (float4*)&g_he[(size_t)(e0 + r) * HD + ch];
    const float* stRow = &stag[r * LDS_F + ch];
#pragma unroll 4
    for (int c = 0; c < 16; ++c) {
        float4 st = *(const float4*)(stRow + 4 * c);
        float4 b  = *(const float4*)&sB[ch + 4 * c];
        float4 o;
        o.x = st.x + b.x; o.y = st.y + b.y; o.z = st.z + b.z; o.w = st.w + b.w;
#pragma unroll
        for (int j = 0; j < 6; ++j) {
            float4 w2 = *(const float4*)&sW2[j * HD + ch + 4 * c];
            o.x += ev[j] * w2.x; o.y += ev[j] * w2.y; o.z += ev[j] * w2.z; o.w += ev[j] * w2.w;
        }
        o.x = fmaxf(o.x, 0.f); o.y = fmaxf(o.y, 0.f); o.z = fmaxf(o.z, 0.f); o.w = fmaxf(o.w, 0.f);
        hePtr[c] = o;
    }
}

// ---------------------------------------------------------------- agg: agg[n] = sum he[in(n)]
__global__ void __launch_bounds__(256) agg_kernel() {
    int node = (blockIdx.x * blockDim.x + threadIdx.x) >> 5;
    int lane = threadIdx.x & 31;
    if (node >= NN) return;
    int start = g_off[node];
    int d = g_deg[node];
    float4 acc = make_float4(0.f, 0.f, 0.f, 0.f);
    for (int j = 0; j < d; ++j) {
        int e = g_csr[start + j];
        float4 v = reinterpret_cast<const float4*>(&g_he[(size_t)e * HD])[lane];
        acc.x += v.x; acc.y += v.y; acc.z += v.z; acc.w += v.w;
    }
    reinterpret_cast<float4*>(&g_agg[(size_t)node * HD])[lane] = acc;
}

// ---------------------------------------------------------------- layer GEMM (no scatter)
__global__ void __launch_bounds__(NTHR) gemm_kernel(
    const float* __restrict__ W, const float* __restrict__ bias,
    const int* __restrict__ src)
{
    extern __shared__ char sm[];
    __nv_bfloat16* sAhi = (__nv_bfloat16*)(sm + OFF_AHI);
    __nv_bfloat16* sAlo = (__nv_bfloat16*)(sm + OFF_ALO);
    float* sB = (float*)(sm + OFF_B);
    int* sSrc = (int*)(sm + OFF_SRC_L);
    float* stag = (float*)(sm + OFF_AHI);

    int tid = threadIdx.x;
    int e0 = blockIdx.x * TE;

    load_W_split(sm, W);
    if (tid < HD) sB[tid] = bias[tid];
    if (tid < TE) sSrc[tid] = src[e0 + tid];
    __syncthreads();

    int r = tid >> 1, ch = (tid & 1) * 64;
    {
        const float4* a = (const float4*)&g_agg[(size_t)sSrc[r] * HD + ch];
        const float4* hr = (const float4*)&g_he[(size_t)(e0 + (r ^ 1)) * HD + ch];
        __nv_bfloat16* dh = &sAhi[r * LDA + ch];
        __nv_bfloat16* dl = &sAlo[r * LDA + ch];
#pragma unroll
        for (int c = 0; c < 16; ++c) {
            float4 av = a[c]; float4 hv = hr[c];
            split_store(dh + 4 * c + 0, dl + 4 * c + 0, av.x - hv.x);
            split_store(dh + 4 * c + 1, dl + 4 * c + 1, av.y - hv.y);
            split_store(dh + 4 * c + 2, dl + 4 * c + 2, av.z - hv.z);
            split_store(dh + 4 * c + 3, dl + 4 * c + 3, av.w - hv.w);
        }
    }
    __syncthreads();

    mma_core(sm);

    float4* hePtr = (float4*)&g_he[(size_t)(e0 + r) * HD + ch];
    const float* stRow = &stag[r * LDS_F + ch];
#pragma unroll 4
    for (int c = 0; c < 16; ++c) {
        float4 st = *(const float4*)(stRow + 4 * c);
        float4 b  = *(const float4*)&sB[ch + 4 * c];
        float4 hv = hePtr[c];
        float4 o;
        o.x = fmaxf(st.x + b.x, 0.f) + hv.x;
        o.y = fmaxf(st.y + b.y, 0.f) + hv.y;
        o.z = fmaxf(st.z + b.z, 0.f) + hv.z;
        o.w = fmaxf(st.w + b.w, 0.f) + hv.w;
        hePtr[c] = o;
    }
}

// ---------------------------------------------------------------- wrp / outinit / readout
__global__ void wrp_kernel(const float* __restrict__ Wro, const float* __restrict__ Wpred) {
    __shared__ float sp[HD];
    int i = threadIdx.x;
    sp[i] = Wpred[i];
    __syncthreads();
    float a = 0.f;
    for (int j = 0; j < HD; ++j) a += Wro[(size_t)i * HD + j] * sp[j];
    g_wrp[i] = a;
}

__global__ void outinit_kernel(float* __restrict__ out, const float* __restrict__ bpred) {
    int i = blockIdx.x * blockDim.x + threadIdx.x;
    if (i < NGB) out[i] = bpred[0];
}

// Final aggregation fused with readout: out[gid[n]] += dot(sum he[in(n)], wrp)
__global__ void __launch_bounds__(256) readout_kernel(
    const int* __restrict__ gid, float* __restrict__ out)
{
    int node = (blockIdx.x * blockDim.x + threadIdx.x) >> 5;
    int lane = threadIdx.x & 31;
    if (node >= NN) return;
    int start = g_off[node];
    int d = g_deg[node];
    float4 acc = make_float4(0.f, 0.f, 0.f, 0.f);
    for (int j = 0; j < d; ++j) {
        int e = g_csr[start + j];
        float4 v = reinterpret_cast<const float4*>(&g_he[(size_t)e * HD])[lane];
        acc.x += v.x; acc.y += v.y; acc.z += v.z; acc.w += v.w;
    }
    float4 w = reinterpret_cast<const float4*>(g_wrp)[lane];
    float s = acc.x * w.x + acc.y * w.y + acc.z * w.z + acc.w * w.w;
#pragma unroll
    for (int o = 16; o; o >>= 1) s += __shfl_xor_sync(0xFFFFFFFFu, s, o);
    if (lane == 0) atomicAdd(&out[gid[node]], s);
}

// ---------------------------------------------------------------- launch
extern "C" void kernel_launch(void* const* d_in, const int* in_sizes, int n_in,
                              void* d_out, int out_size)
{
    const float* h      = (const float*)d_in[0];
    const float* e      = (const float*)d_in[1];
    const float* Wemb   = (const float*)d_in[2];
    const float* Winit  = (const float*)d_in[3];
    const float* binit  = (const float*)d_in[4];
    const float* Wlay   = (const float*)d_in[5];
    const float* blay   = (const float*)d_in[6];
    const float* Wro    = (const float*)d_in[7];
    const float* Wpred  = (const float*)d_in[8];
    const float* bpred  = (const float*)d_in[9];
    const int*   src    = (const int*)d_in[10];
    const int*   dst    = (const int*)d_in[11];
    const int*   gid    = (const int*)d_in[12];
    float* out = (float*)d_out;

    cudaFuncSetAttribute(init_kernel, cudaFuncAttributeMaxDynamicSharedMemorySize, SMEM_INIT);
    cudaFuncSetAttribute(gemm_kernel, cudaFuncAttributeMaxDynamicSharedMemorySize, SMEM_GEMM);

    const int edgeBlocks = NE / TE;       // 3125
    const int embedBlocks = NN / 64;      // 3125
    const int nodeWarpBlocks = (NN * 32 + 255) / 256;  // 25000

    // order chosen so launch index 5 (ncu -s 5 -c 1) = init_kernel (GEMM)
    zero_deg_kernel<<<(NN + 255) / 256, 256>>>();                    // 0
    embed_kernel<<<embedBlocks, 128>>>(h, Wemb);                     // 1
    deg_count_kernel<<<(NE + 255) / 256, 256>>>(dst);                // 2
    scan_a_kernel<<<NSCAN, SCANB>>>();                               // 3
    scan_b_kernel<<<1, 32>>>();                                      // 4
    init_kernel<<<edgeBlocks, NTHR, SMEM_INIT>>>(Winit, binit, e, src);  // 5 <- profiled
    scan_c_kernel<<<NSCAN, SCANB>>>();                               // 6
    csr_fill_kernel<<<(NE + 255) / 256, 256>>>(dst);                 // 7

    for (int l = 0; l < 4; ++l) {
        agg_kernel<<<nodeWarpBlocks, 256>>>();
        gemm_kernel<<<edgeBlocks, NTHR, SMEM_GEMM>>>(
            Wlay + (size_t)l * HD * HD, blay + (size_t)l * HD, src);
    }

    wrp_kernel<<<1, HD>>>(Wro, Wpred);
    outinit_kernel<<<(NGB + 255) / 256, 256>>>(out, bpred);
    readout_kernel<<<nodeWarpBlocks, 256>>>(gid, out);
}

// round 6
// speedup vs baseline: 1.5502x; 1.3124x over previous
#include <cuda_runtime.h>
#include <cuda_bf16.h>
#include <mma.h>

using namespace nvcuda;

// D-MPNN on GB300. Round 6: persistent TE=64 GEMM blocks, 2 CTAs/SM,
// W split once per block, fragment-level epilogue (no staging), init
// folded into the same GEMM via K-padding to 144.

#define NN 200000
#define NE 800000
#define HD 128
#define NGB 2000
#define TE 64
#define NTILES (NE / TE)        // 12500
#define SCANB 512
#define NSCAN ((NN + SCANB - 1) / SCANB)

__device__ float g_x[(size_t)NN * HD];
__device__ float g_he[(size_t)NE * HD];
__device__ float g_agg[(size_t)NN * HD];
__device__ float g_wrp[HD];
__device__ int g_deg[NN];
__device__ int g_off[NN];
__device__ int g_cursor[NN];
__device__ int g_csr[NE];
__device__ int g_bsum[NSCAN];

__device__ __forceinline__ void split_store(__nv_bfloat16* hi, __nv_bfloat16* lo, float v) {
    __nv_bfloat16 h = __float2bfloat16_rn(v);
    *hi = h;
    *lo = __float2bfloat16_rn(v - __bfloat162float(h));
}

// ---------------------------------------------------------------- CSR build
__global__ void zero_deg_kernel() {
    int i = blockIdx.x * blockDim.x + threadIdx.x;
    if (i < NN) g_deg[i] = 0;
}
__global__ void deg_count_kernel(const int* __restrict__ dst) {
    int k = blockIdx.x * blockDim.x + threadIdx.x;
    if (k < NE) atomicAdd(&g_deg[dst[k]], 1);
}
__global__ void scan_a_kernel() {
    __shared__ int s[SCANB];
    int t = threadIdx.x;
    int n = blockIdx.x * SCANB + t;
    s[t] = (n < NN) ? g_deg[n] : 0;
    __syncthreads();
    for (int o = SCANB / 2; o > 0; o >>= 1) {
        if (t < o) s[t] += s[t + o];
        __syncthreads();
    }
    if (t == 0) g_bsum[blockIdx.x] = s[0];
}
__global__ void scan_b_kernel() {
    if (threadIdx.x == 0) {
        int run = 0;
        for (int b = 0; b < NSCAN; ++b) { int v = g_bsum[b]; g_bsum[b] = run; run += v; }
    }
}
__global__ void scan_c_kernel() {
    __shared__ int s[SCANB];
    int t = threadIdx.x;
    int n = blockIdx.x * SCANB + t;
    int val = (n < NN) ? g_deg[n] : 0;
    s[t] = val;
    __syncthreads();
    for (int o = 1; o < SCANB; o <<= 1) {
        int x = (t >= o) ? s[t - o] : 0;
        __syncthreads();
        s[t] += x;
        __syncthreads();
    }
    if (n < NN) {
        int off = g_bsum[blockIdx.x] + s[t] - val;
        g_off[n] = off;
        g_cursor[n] = off;
    }
}
__global__ void csr_fill_kernel(const int* __restrict__ dst) {
    int k = blockIdx.x * blockDim.x + threadIdx.x;
    if (k < NE) {
        int pos = atomicAdd(&g_cursor[dst[k]], 1);
        g_csr[pos] = k;
    }
}

// ---------------------------------------------------------------- embed
__global__ void __launch_bounds__(128) embed_kernel(
    const float* __restrict__ h, const float* __restrict__ Wemb)
{
    __shared__ float sh[64 * 28];
    int n0 = blockIdx.x * 64;
    int tid = threadIdx.x;
    for (int idx = tid; idx < 64 * 28; idx += 128)
        sh[idx] = h[(size_t)n0 * 28 + idx];
    __syncthreads();
    float w[28];
#pragma unroll
    for (int i = 0; i < 28; ++i) w[i] = Wemb[i * HD + tid];
    for (int n = 0; n < 64; ++n) {
        float acc = 0.f;
#pragma unroll
        for (int i = 0; i < 28; ++i) acc += sh[n * 28 + i] * w[i];
        g_x[(size_t)(n0 + n) * HD + tid] = acc;
    }
}

// ---------------------------------------------------------------- unified GEMM
// KT: K tiles (8 = layer, 9 = init with e-padding). LD: A leading dim.
// IS_INIT: A = [x[src], e, 0pad]; else A = agg[src] - he[rev], residual add.
template<int KT, int LD, int MINB, bool IS_INIT>
__global__ void __launch_bounds__(256, MINB) mpnn_gemm_kernel(
    const float* __restrict__ W, const float* __restrict__ bias,
    const float* __restrict__ eAttr, const int* __restrict__ src)
{
    extern __shared__ char sm[];
    const int KR = KT * 16;
    __nv_bfloat16* sAhi = (__nv_bfloat16*)sm;
    __nv_bfloat16* sAlo = sAhi + TE * LD;
    __nv_bfloat16* sWhi = sAlo + TE * LD;
    __nv_bfloat16* sWlo = sWhi + KR * 136;
    float* sBias = (float*)(sWlo + KR * 136);    // 16 x 128 broadcast

    int tid = threadIdx.x;
    const int realRows = IS_INIT ? 134 : 128;

    // split W into smem once per persistent block
    for (int i = tid; i < KR * 128; i += 256) {
        int k = i >> 7, n = i & 127;
        float v = (k < realRows) ? W[k * 128 + n] : 0.f;
        split_store(&sWhi[k * 136 + n], &sWlo[k * 136 + n], v);
    }
    for (int i = tid; i < 16 * 128; i += 256) sBias[i] = bias[i & 127];
    __syncthreads();

    int w = tid >> 5;
    int mg = w >> 1;                 // 4 row groups of 16
    int ncol = (w & 1) * 64;         // 2 col halves
    int r = tid >> 2;                // gather row 0..63
    int q = tid & 3;                 // gather col group (32 floats)

    for (int t = blockIdx.x; t < NTILES; t += gridDim.x) {
        int e0 = t * TE;

        // ---- gather ----
        {
            int s = __ldg(&src[e0 + r]);
            __nv_bfloat16* dh = &sAhi[r * LD + q * 32];
            __nv_bfloat16* dl = &sAlo[r * LD + q * 32];
            if (IS_INIT) {
                const float4* a = (const float4*)&g_x[(size_t)s * HD + q * 32];
#pragma unroll
                for (int c = 0; c < 8; ++c) {
                    float4 v = a[c];
                    split_store(dh + 4 * c + 0, dl + 4 * c + 0, v.x);
                    split_store(dh + 4 * c + 1, dl + 4 * c + 1, v.y);
                    split_store(dh + 4 * c + 2, dl + 4 * c + 2, v.z);
                    split_store(dh + 4 * c + 3, dl + 4 * c + 3, v.w);
                }
                if (q == 0) {  // e-extension cols 128..143
                    __nv_bfloat16* eh = &sAhi[r * LD + 128];
                    __nv_bfloat16* el = &sAlo[r * LD + 128];
#pragma unroll
                    for (int j = 0; j < 16; ++j) {
                        float v = (j < 6) ? __ldg(&eAttr[(size_t)(e0 + r) * 6 + j]) : 0.f;
                        split_store(eh + j, el + j, v);
                    }
                }
            } else {
                const float4* a = (const float4*)&g_agg[(size_t)s * HD + q * 32];
                const float4* h = (const float4*)&g_he[(size_t)(e0 + (r ^ 1)) * HD + q * 32];
#pragma unroll
                for (int c = 0; c < 8; ++c) {
                    float4 av = a[c]; float4 hv = h[c];
                    split_store(dh + 4 * c + 0, dl + 4 * c + 0, av.x - hv.x);
                    split_store(dh + 4 * c + 1, dl + 4 * c + 1, av.y - hv.y);
                    split_store(dh + 4 * c + 2, dl + 4 * c + 2, av.z - hv.z);
                    split_store(dh + 4 * c + 3, dl + 4 * c + 3, av.w - hv.w);
                }
            }
        }
        __syncthreads();

        // ---- MMA: acc initialized from bias tile ----
        wmma::fragment<wmma::accumulator, 16, 16, 16, float> acc[4];
#pragma unroll
        for (int nt = 0; nt < 4; ++nt)
            wmma::load_matrix_sync(acc[nt], sBias + ncol + nt * 16, 128, wmma::mem_row_major);

#pragma unroll
        for (int kt = 0; kt < KT; ++kt) {
            wmma::fragment<wmma::matrix_a, 16, 16, 16, __nv_bfloat16, wmma::row_major> ahi, alo;
            wmma::load_matrix_sync(ahi, sAhi + mg * 16 * LD + kt * 16, LD);
            wmma::load_matrix_sync(alo, sAlo + mg * 16 * LD + kt * 16, LD);
#pragma unroll
            for (int nt = 0; nt < 4; ++nt) {
                wmma::fragment<wmma::matrix_b, 16, 16, 16, __nv_bfloat16, wmma::row_major> bhi, blo;
                wmma::load_matrix_sync(bhi, sWhi + kt * 16 * 136 + ncol + nt * 16, 136);
                wmma::load_matrix_sync(blo, sWlo + kt * 16 * 136 + ncol + nt * 16, 136);
                wmma::mma_sync(acc[nt], ahi, bhi, acc[nt]);
                wmma::mma_sync(acc[nt], alo, bhi, acc[nt]);
                wmma::mma_sync(acc[nt], ahi, blo, acc[nt]);
            }
        }
        __syncthreads();   // MMA reads of sA done before next gather overwrites

        // ---- epilogue on fragments ----
        float* base = &g_he[(size_t)(e0 + mg * 16) * HD + ncol];
#pragma unroll
        for (int nt = 0; nt < 4; ++nt) {
#pragma unroll
            for (int i = 0; i < acc[nt].num_elements; ++i)
                acc[nt].x[i] = fmaxf(acc[nt].x[i], 0.f);
            if (!IS_INIT) {
                wmma::fragment<wmma::accumulator, 16, 16, 16, float> hf;
                wmma::load_matrix_sync(hf, base + nt * 16, HD, wmma::mem_row_major);
#pragma unroll
                for (int i = 0; i < acc[nt].num_elements; ++i)
                    acc[nt].x[i] += hf.x[i];
            }
            wmma::store_matrix_sync(base + nt * 16, acc[nt], HD, wmma::mem_row_major);
        }
    }
}

// smem sizes
#define SMEM_LAYER ((size_t)(2 * TE * 136 + 2 * 128 * 136) * 2 + 16 * 128 * 4)   // 112,640
#define SMEM_INIT  ((size_t)(2 * TE * 152 + 2 * 144 * 136) * 2 + 16 * 128 * 4)   // 125,440

// ---------------------------------------------------------------- agg
__global__ void __launch_bounds__(256) agg_kernel() {
    int node = (blockIdx.x * blockDim.x + threadIdx.x) >> 5;
    int lane = threadIdx.x & 31;
    if (node >= NN) return;
    int start = g_off[node];
    int d = g_deg[node];
    float4 acc = make_float4(0.f, 0.f, 0.f, 0.f);
    for (int j = 0; j < d; ++j) {
        int e = g_csr[start + j];
        float4 v = reinterpret_cast<const float4*>(&g_he[(size_t)e * HD])[lane];
        acc.x += v.x; acc.y += v.y; acc.z += v.z; acc.w += v.w;
    }
    reinterpret_cast<float4*>(&g_agg[(size_t)node * HD])[lane] = acc;
}

// ---------------------------------------------------------------- wrp / outinit / readout
__global__ void wrp_kernel(const float* __restrict__ Wro, const float* __restrict__ Wpred) {
    __shared__ float sp[HD];
    int i = threadIdx.x;
    sp[i] = Wpred[i];
    __syncthreads();
    float a = 0.f;
    for (int j = 0; j < HD; ++j) a += Wro[(size_t)i * HD + j] * sp[j];
    g_wrp[i] = a;
}
__global__ void outinit_kernel(float* __restrict__ out, const float* __restrict__ bpred) {
    int i = blockIdx.x * blockDim.x + threadIdx.x;
    if (i < NGB) out[i] = bpred[0];
}
__global__ void __launch_bounds__(256) readout_kernel(
    const int* __restrict__ gid, float* __restrict__ out)
{
    int node = (blockIdx.x * blockDim.x + threadIdx.x) >> 5;
    int lane = threadIdx.x & 31;
    if (node >= NN) return;
    int start = g_off[node];
    int d = g_deg[node];
    float4 acc = make_float4(0.f, 0.f, 0.f, 0.f);
    for (int j = 0; j < d; ++j) {
        int e = g_csr[start + j];
        float4 v = reinterpret_cast<const float4*>(&g_he[(size_t)e * HD])[lane];
        acc.x += v.x; acc.y += v.y; acc.z += v.z; acc.w += v.w;
    }
    float4 w = reinterpret_cast<const float4*>(g_wrp)[lane];
    float s = acc.x * w.x + acc.y * w.y + acc.z * w.z + acc.w * w.w;
#pragma unroll
    for (int o = 16; o; o >>= 1) s += __shfl_xor_sync(0xFFFFFFFFu, s, o);
    if (lane == 0) atomicAdd(&out[gid[node]], s);
}

// ---------------------------------------------------------------- launch
extern "C" void kernel_launch(void* const* d_in, const int* in_sizes, int n_in,
                              void* d_out, int out_size)
{
    const float* h      = (const float*)d_in[0];
    const float* e      = (const float*)d_in[1];
    const float* Wemb   = (const float*)d_in[2];
    const float* Winit  = (const float*)d_in[3];
    const float* binit  = (const float*)d_in[4];
    const float* Wlay   = (const float*)d_in[5];
    const float* blay   = (const float*)d_in[6];
    const float* Wro    = (const float*)d_in[7];
    const float* Wpred  = (const float*)d_in[8];
    const float* bpred  = (const float*)d_in[9];
    const int*   src    = (const int*)d_in[10];
    const int*   dst    = (const int*)d_in[11];
    const int*   gid    = (const int*)d_in[12];
    float* out = (float*)d_out;

    auto initK  = mpnn_gemm_kernel<9, 152, 1, true>;
    auto layerK = mpnn_gemm_kernel<8, 136, 2, false>;
    cudaFuncSetAttribute(initK,  cudaFuncAttributeMaxDynamicSharedMemorySize, (int)SMEM_INIT);
    cudaFuncSetAttribute(layerK, cudaFuncAttributeMaxDynamicSharedMemorySize, (int)SMEM_LAYER);

    const int embedBlocks = NN / 64;
    const int nodeWarpBlocks = (NN * 32 + 255) / 256;

    // launch order: profiled capture lands on our index 3 -> init GEMM
    zero_deg_kernel<<<(NN + 255) / 256, 256>>>();                    // 0
    deg_count_kernel<<<(NE + 255) / 256, 256>>>(dst);                // 1
    embed_kernel<<<embedBlocks, 128>>>(h, Wemb);                     // 2
    initK<<<148, 256, SMEM_INIT>>>(Winit, binit, e, src);            // 3 <- profiled
    scan_a_kernel<<<NSCAN, SCANB>>>();                               // 4
    scan_b_kernel<<<1, 32>>>();                                      // 5
    scan_c_kernel<<<NSCAN, SCANB>>>();                               // 6
    csr_fill_kernel<<<(NE + 255) / 256, 256>>>(dst);                 // 7

    for (int l = 0; l < 4; ++l) {
        agg_kernel<<<nodeWarpBlocks, 256>>>();
        layerK<<<296, 256, SMEM_LAYER>>>(
            Wlay + (size_t)l * HD * HD, blay + (size_t)l * HD, nullptr, src);
    }

    wrp_kernel<<<1, HD>>>(Wro, Wpred);
    outinit_kernel<<<(NGB + 255) / 256, 256>>>(out, bpred);
    readout_kernel<<<nodeWarpBlocks, 256>>>(gid, out);
}

// round 7
// speedup vs baseline: 1.7609x; 1.1359x over previous
#include <cuda_runtime.h>
#include <cuda_bf16.h>
#include <mma.h>

using namespace nvcuda;

// D-MPNN on GB300. Round 7: 2 CTAs/SM for BOTH GEMMs (init TE=32),
// layer warp tile 32x32 (less LDS per MMA), hoisted residual loads,
// packed bf162 gather stores.

#define NN 200000
#define NE 800000
#define HD 128
#define NGB 2000
#define SCANB 512
#define NSCAN ((NN + SCANB - 1) / SCANB)

__device__ float g_x[(size_t)NN * HD];
__device__ float g_he[(size_t)NE * HD];
__device__ float g_agg[(size_t)NN * HD];
__device__ float g_wrp[HD];
__device__ int g_deg[NN];
__device__ int g_off[NN];
__device__ int g_cursor[NN];
__device__ int g_csr[NE];
__device__ int g_bsum[NSCAN];

__device__ __forceinline__ __nv_bfloat162 pack_hi(float a, float b) {
    return __nv_bfloat162(__float2bfloat16_rn(a), __float2bfloat16_rn(b));
}
__device__ __forceinline__ __nv_bfloat162 pack_lo(float a, float b, __nv_bfloat162 hi) {
    return __nv_bfloat162(__float2bfloat16_rn(a - __bfloat162float(hi.x)),
                          __float2bfloat16_rn(b - __bfloat162float(hi.y)));
}

// ---------------------------------------------------------------- CSR build
__global__ void zero_deg_kernel() {
    int i = blockIdx.x * blockDim.x + threadIdx.x;
    if (i < NN) g_deg[i] = 0;
}
__global__ void deg_count_kernel(const int* __restrict__ dst) {
    int k = blockIdx.x * blockDim.x + threadIdx.x;
    if (k < NE) atomicAdd(&g_deg[dst[k]], 1);
}
__global__ void scan_a_kernel() {
    __shared__ int s[SCANB];
    int t = threadIdx.x;
    int n = blockIdx.x * SCANB + t;
    s[t] = (n < NN) ? g_deg[n] : 0;
    __syncthreads();
    for (int o = SCANB / 2; o > 0; o >>= 1) {
        if (t < o) s[t] += s[t + o];
        __syncthreads();
    }
    if (t == 0) g_bsum[blockIdx.x] = s[0];
}
__global__ void scan_b_kernel() {
    if (threadIdx.x == 0) {
        int run = 0;
        for (int b = 0; b < NSCAN; ++b) { int v = g_bsum[b]; g_bsum[b] = run; run += v; }
    }
}
__global__ void scan_c_kernel() {
    __shared__ int s[SCANB];
    int t = threadIdx.x;
    int n = blockIdx.x * SCANB + t;
    int val = (n < NN) ? g_deg[n] : 0;
    s[t] = val;
    __syncthreads();
    for (int o = 1; o < SCANB; o <<= 1) {
        int x = (t >= o) ? s[t - o] : 0;
        __syncthreads();
        s[t] += x;
        __syncthreads();
    }
    if (n < NN) {
        int off = g_bsum[blockIdx.x] + s[t] - val;
        g_off[n] = off;
        g_cursor[n] = off;
    }
}
__global__ void csr_fill_kernel(const int* __restrict__ dst) {
    int k = blockIdx.x * blockDim.x + threadIdx.x;
    if (k < NE) {
        int pos = atomicAdd(&g_cursor[dst[k]], 1);
        g_csr[pos] = k;
    }
}

// ---------------------------------------------------------------- embed
__global__ void __launch_bounds__(128) embed_kernel(
    const float* __restrict__ h, const float* __restrict__ Wemb)
{
    __shared__ float sh[64 * 28];
    int n0 = blockIdx.x * 64;
    int tid = threadIdx.x;
    for (int idx = tid; idx < 64 * 28; idx += 128)
        sh[idx] = h[(size_t)n0 * 28 + idx];
    __syncthreads();
    float w[28];
#pragma unroll
    for (int i = 0; i < 28; ++i) w[i] = Wemb[i * HD + tid];
    for (int n = 0; n < 64; ++n) {
        float acc = 0.f;
#pragma unroll
        for (int i = 0; i < 28; ++i) acc += sh[n * 28 + i] * w[i];
        g_x[(size_t)(n0 + n) * HD + tid] = acc;
    }
}

// ---------------------------------------------------------------- layer GEMM
// TE=64, 256 threads, 2 CTAs/SM. Warp tile 32x32. Persistent; W split once.
#define LTE 64
#define LNT (NE / LTE)          // 12500
#define SMEM_LAYER ((2 * LTE * 136 + 2 * 128 * 136) * 2 + 16 * 128 * 4)  // 112,640

__global__ void __launch_bounds__(256, 2) layer_kernel(
    const float* __restrict__ W, const float* __restrict__ bias,
    const int* __restrict__ src)
{
    extern __shared__ char sm[];
    __nv_bfloat16* sAhi = (__nv_bfloat16*)sm;
    __nv_bfloat16* sAlo = sAhi + LTE * 136;
    __nv_bfloat16* sWhi = sAlo + LTE * 136;
    __nv_bfloat16* sWlo = sWhi + 128 * 136;
    float* sBias = (float*)(sWlo + 128 * 136);

    int tid = threadIdx.x;
    for (int i = tid; i < 128 * 128; i += 256) {
        int k = i >> 7, n = i & 127;
        float v = W[i];
        __nv_bfloat16 h = __float2bfloat16_rn(v);
        sWhi[k * 136 + n] = h;
        sWlo[k * 136 + n] = __float2bfloat16_rn(v - __bfloat162float(h));
    }
    for (int i = tid; i < 16 * 128; i += 256) sBias[i] = bias[i & 127];
    __syncthreads();

    int w = tid >> 5;
    int mg = (w >> 2) * 32;          // 2 groups of 32 rows
    int cq = (w & 3) * 32;           // 4 col quarters of 32
    int r = tid >> 2;                // gather row 0..63
    int q = (tid & 3) * 32;          // gather col chunk

    for (int t = blockIdx.x; t < LNT; t += gridDim.x) {
        int e0 = t * LTE;

        // ---- gather m = agg[src] - he[rev], packed bf162 stores ----
        {
            int s = __ldg(&src[e0 + r]);
            const float4* a = (const float4*)&g_agg[(size_t)s * HD + q];
            const float4* h = (const float4*)&g_he[(size_t)(e0 + (r ^ 1)) * HD + q];
            __nv_bfloat162* dh = (__nv_bfloat162*)&sAhi[r * 136 + q];
            __nv_bfloat162* dl = (__nv_bfloat162*)&sAlo[r * 136 + q];
#pragma unroll
            for (int c = 0; c < 8; ++c) {
                float4 av = a[c]; float4 hv = h[c];
                float m0 = av.x - hv.x, m1 = av.y - hv.y;
                float m2 = av.z - hv.z, m3 = av.w - hv.w;
                __nv_bfloat162 h01 = pack_hi(m0, m1);
                __nv_bfloat162 h23 = pack_hi(m2, m3);
                dh[2 * c]     = h01;
                dh[2 * c + 1] = h23;
                dl[2 * c]     = pack_lo(m0, m1, h01);
                dl[2 * c + 1] = pack_lo(m2, m3, h23);
            }
        }
        __syncthreads();

        // ---- residual loads hoisted (LDGs overlap MMA) ----
        float* base0 = &g_he[(size_t)(e0 + mg) * HD + cq];
        wmma::fragment<wmma::accumulator, 16, 16, 16, float> hf[2][2];
#pragma unroll
        for (int i = 0; i < 2; ++i)
#pragma unroll
            for (int nt = 0; nt < 2; ++nt)
                wmma::load_matrix_sync(hf[i][nt], base0 + (size_t)i * 16 * HD + nt * 16,
                                       HD, wmma::mem_row_major);

        wmma::fragment<wmma::accumulator, 16, 16, 16, float> acc[2][2];
#pragma unroll
        for (int i = 0; i < 2; ++i)
#pragma unroll
            for (int nt = 0; nt < 2; ++nt)
                wmma::load_matrix_sync(acc[i][nt], sBias + cq + nt * 16, 128, wmma::mem_row_major);

#pragma unroll
        for (int kt = 0; kt < 8; ++kt) {
            wmma::fragment<wmma::matrix_a, 16, 16, 16, __nv_bfloat16, wmma::row_major> ahi[2], alo[2];
#pragma unroll
            for (int i = 0; i < 2; ++i) {
                wmma::load_matrix_sync(ahi[i], sAhi + (mg + 16 * i) * 136 + kt * 16, 136);
                wmma::load_matrix_sync(alo[i], sAlo + (mg + 16 * i) * 136 + kt * 16, 136);
            }
#pragma unroll
            for (int nt = 0; nt < 2; ++nt) {
                wmma::fragment<wmma::matrix_b, 16, 16, 16, __nv_bfloat16, wmma::row_major> bhi, blo;
                wmma::load_matrix_sync(bhi, sWhi + kt * 16 * 136 + cq + nt * 16, 136);
                wmma::load_matrix_sync(blo, sWlo + kt * 16 * 136 + cq + nt * 16, 136);
#pragma unroll
                for (int i = 0; i < 2; ++i) {
                    wmma::mma_sync(acc[i][nt], ahi[i], bhi, acc[i][nt]);
                    wmma::mma_sync(acc[i][nt], alo[i], bhi, acc[i][nt]);
                    wmma::mma_sync(acc[i][nt], ahi[i], blo, acc[i][nt]);
                }
            }
        }
        __syncthreads();   // MMA reads done before next gather overwrites sA

        // ---- epilogue: relu + residual ----
#pragma unroll
        for (int i = 0; i < 2; ++i)
#pragma unroll
            for (int nt = 0; nt < 2; ++nt) {
#pragma unroll
                for (int x = 0; x < acc[i][nt].num_elements; ++x)
                    acc[i][nt].x[x] = fmaxf(acc[i][nt].x[x], 0.f) + hf[i][nt].x[x];
                wmma::store_matrix_sync(base0 + (size_t)i * 16 * HD + nt * 16,
                                        acc[i][nt], HD, wmma::mem_row_major);
            }
    }
}

// ---------------------------------------------------------------- init GEMM
// TE=32, KT=9 (K padded to 144: cols 128..133 = e), 2 CTAs/SM.
#define ITE 32
#define INT_ (NE / ITE)         // 25000
#define SMEM_INIT ((2 * ITE * 152 + 2 * 144 * 136) * 2 + 16 * 128 * 4)  // 105,984

__global__ void __launch_bounds__(256, 2) init_kernel(
    const float* __restrict__ W, const float* __restrict__ bias,
    const float* __restrict__ eAttr, const int* __restrict__ src)
{
    extern __shared__ char sm[];
    __nv_bfloat16* sAhi = (__nv_bfloat16*)sm;
    __nv_bfloat16* sAlo = sAhi + ITE * 152;
    __nv_bfloat16* sWhi = sAlo + ITE * 152;
    __nv_bfloat16* sWlo = sWhi + 144 * 136;
    float* sBias = (float*)(sWlo + 144 * 136);

    int tid = threadIdx.x;
    for (int i = tid; i < 144 * 128; i += 256) {
        int k = i >> 7, n = i & 127;
        float v = (k < 134) ? W[k * 128 + n] : 0.f;
        __nv_bfloat16 h = __float2bfloat16_rn(v);
        sWhi[k * 136 + n] = h;
        sWlo[k * 136 + n] = __float2bfloat16_rn(v - __bfloat162float(h));
    }
    for (int i = tid; i < 16 * 128; i += 256) sBias[i] = bias[i & 127];
    __syncthreads();

    int w = tid >> 5;
    int mg = (w >> 2) * 16;          // 2 groups of 16 rows
    int cq = (w & 3) * 32;           // 4 col quarters
    int r = tid >> 3;                // gather row 0..31
    int q = (tid & 7) * 16;          // gather col chunk of 16

    for (int t = blockIdx.x; t < INT_; t += gridDim.x) {
        int e0 = t * ITE;

        // ---- gather [x[src], e, pad] ----
        {
            int s = __ldg(&src[e0 + r]);
            const float4* a = (const float4*)&g_x[(size_t)s * HD + q];
            __nv_bfloat162* dh = (__nv_bfloat162*)&sAhi[r * 152 + q];
            __nv_bfloat162* dl = (__nv_bfloat162*)&sAlo[r * 152 + q];
#pragma unroll
            for (int c = 0; c < 4; ++c) {
                float4 v = a[c];
                __nv_bfloat162 h01 = pack_hi(v.x, v.y);
                __nv_bfloat162 h23 = pack_hi(v.z, v.w);
                dh[2 * c]     = h01;
                dh[2 * c + 1] = h23;
                dl[2 * c]     = pack_lo(v.x, v.y, h01);
                dl[2 * c + 1] = pack_lo(v.z, v.w, h23);
            }
            if ((tid & 7) == 0) {  // cols 128..143: 6 e-values + 10 zeros
                __nv_bfloat162* eh = (__nv_bfloat162*)&sAhi[r * 152 + 128];
                __nv_bfloat162* el = (__nv_bfloat162*)&sAlo[r * 152 + 128];
                const float* ep = &eAttr[(size_t)(e0 + r) * 6];
#pragma unroll
                for (int c = 0; c < 8; ++c) {
                    float a0 = (2 * c < 6) ? __ldg(ep + 2 * c) : 0.f;
                    float a1 = (2 * c + 1 < 6) ? __ldg(ep + 2 * c + 1) : 0.f;
                    __nv_bfloat162 hh = pack_hi(a0, a1);
                    eh[c] = hh;
                    el[c] = pack_lo(a0, a1, hh);
                }
            }
        }
        __syncthreads();

        wmma::fragment<wmma::accumulator, 16, 16, 16, float> acc[2];
#pragma unroll
        for (int nt = 0; nt < 2; ++nt)
            wmma::load_matrix_sync(acc[nt], sBias + cq + nt * 16, 128, wmma::mem_row_major);

#pragma unroll
        for (int kt = 0; kt < 9; ++kt) {
            wmma::fragment<wmma::matrix_a, 16, 16, 16, __nv_bfloat16, wmma::row_major> ahi, alo;
            wmma::load_matrix_sync(ahi, sAhi + mg * 152 + kt * 16, 152);
            wmma::load_matrix_sync(alo, sAlo + mg * 152 + kt * 16, 152);
#pragma unroll
            for (int nt = 0; nt < 2; ++nt) {
                wmma::fragment<wmma::matrix_b, 16, 16, 16, __nv_bfloat16, wmma::row_major> bhi, blo;
                wmma::load_matrix_sync(bhi, sWhi + kt * 16 * 136 + cq + nt * 16, 136);
                wmma::load_matrix_sync(blo, sWlo + kt * 16 * 136 + cq + nt * 16, 136);
                wmma::mma_sync(acc[nt], ahi, bhi, acc[nt]);
                wmma::mma_sync(acc[nt], alo, bhi, acc[nt]);
                wmma::mma_sync(acc[nt], ahi, blo, acc[nt]);
            }
        }
        __syncthreads();

        float* base = &g_he[(size_t)(e0 + mg) * HD + cq];
#pragma unroll
        for (int nt = 0; nt < 2; ++nt) {
#pragma unroll
            for (int x = 0; x < acc[nt].num_elements; ++x)
                acc[nt].x[x] = fmaxf(acc[nt].x[x], 0.f);
            wmma::store_matrix_sync(base + nt * 16, acc[nt], HD, wmma::mem_row_major);
        }
    }
}

// ---------------------------------------------------------------- agg
__global__ void __launch_bounds__(256) agg_kernel() {
    int node = (blockIdx.x * blockDim.x + threadIdx.x) >> 5;
    int lane = threadIdx.x & 31;
    if (node >= NN) return;
    int start = g_off[node];
    int d = g_deg[node];
    float4 acc = make_float4(0.f, 0.f, 0.f, 0.f);
    for (int j = 0; j < d; ++j) {
        int e = g_csr[start + j];
        float4 v = reinterpret_cast<const float4*>(&g_he[(size_t)e * HD])[lane];
        acc.x += v.x; acc.y += v.y; acc.z += v.z; acc.w += v.w;
    }
    reinterpret_cast<float4*>(&g_agg[(size_t)node * HD])[lane] = acc;
}

// ---------------------------------------------------------------- wrp / outinit / readout
__global__ void wrp_kernel(const float* __restrict__ Wro, const float* __restrict__ Wpred) {
    __shared__ float sp[HD];
    int i = threadIdx.x;
    sp[i] = Wpred[i];
    __syncthreads();
    float a = 0.f;
    for (int j = 0; j < HD; ++j) a += Wro[(size_t)i * HD + j] * sp[j];
    g_wrp[i] = a;
}
__global__ void outinit_kernel(float* __restrict__ out, const float* __restrict__ bpred) {
    int i = blockIdx.x * blockDim.x + threadIdx.x;
    if (i < NGB) out[i] = bpred[0];
}
__global__ void __launch_bounds__(256) readout_kernel(
    const int* __restrict__ gid, float* __restrict__ out)
{
    int node = (blockIdx.x * blockDim.x + threadIdx.x) >> 5;
    int lane = threadIdx.x & 31;
    if (node >= NN) return;
    int start = g_off[node];
    int d = g_deg[node];
    float4 acc = make_float4(0.f, 0.f, 0.f, 0.f);
    for (int j = 0; j < d; ++j) {
        int e = g_csr[start + j];
        float4 v = reinterpret_cast<const float4*>(&g_he[(size_t)e * HD])[lane];
        acc.x += v.x; acc.y += v.y; acc.z += v.z; acc.w += v.w;
    }
    float4 w = reinterpret_cast<const float4*>(g_wrp)[lane];
    float s = acc.x * w.x + acc.y * w.y + acc.z * w.z + acc.w * w.w;
#pragma unroll
    for (int o = 16; o; o >>= 1) s += __shfl_xor_sync(0xFFFFFFFFu, s, o);
    if (lane == 0) atomicAdd(&out[gid[node]], s);
}

// ---------------------------------------------------------------- launch
extern "C" void kernel_launch(void* const* d_in, const int* in_sizes, int n_in,
                              void* d_out, int out_size)
{
    const float* h      = (const float*)d_in[0];
    const float* e      = (const float*)d_in[1];
    const float* Wemb   = (const float*)d_in[2];
    const float* Winit  = (const float*)d_in[3];
    const float* binit  = (const float*)d_in[4];
    const float* Wlay   = (const float*)d_in[5];
    const float* blay   = (const float*)d_in[6];
    const float* Wro    = (const float*)d_in[7];
    const float* Wpred  = (const float*)d_in[8];
    const float* bpred  = (const float*)d_in[9];
    const int*   src    = (const int*)d_in[10];
    const int*   dst    = (const int*)d_in[11];
    const int*   gid    = (const int*)d_in[12];
    float* out = (float*)d_out;

    cudaFuncSetAttribute(init_kernel,  cudaFuncAttributeMaxDynamicSharedMemorySize, SMEM_INIT);
    cudaFuncSetAttribute(layer_kernel, cudaFuncAttributeMaxDynamicSharedMemorySize, SMEM_LAYER);

    const int embedBlocks = NN / 64;
    const int nodeWarpBlocks = (NN * 32 + 255) / 256;

    // captured profile = launch index 3 -> init GEMM
    zero_deg_kernel<<<(NN + 255) / 256, 256>>>();                    // 0
    deg_count_kernel<<<(NE + 255) / 256, 256>>>(dst);                // 1
    embed_kernel<<<embedBlocks, 128>>>(h, Wemb);                     // 2
    init_kernel<<<296, 256, SMEM_INIT>>>(Winit, binit, e, src);      // 3 <- profiled
    scan_a_kernel<<<NSCAN, SCANB>>>();                               // 4
    scan_b_kernel<<<1, 32>>>();                                      // 5
    scan_c_kernel<<<NSCAN, SCANB>>>();                               // 6
    csr_fill_kernel<<<(NE + 255) / 256, 256>>>(dst);                 // 7

    for (int l = 0; l < 4; ++l) {
        agg_kernel<<<nodeWarpBlocks, 256>>>();
        layer_kernel<<<296, 256, SMEM_LAYER>>>(
            Wlay + (size_t)l * HD * HD, blay + (size_t)l * HD, src);
    }

    wrp_kernel<<<1, HD>>>(Wro, Wpred);
    outinit_kernel<<<(NGB + 255) / 256, 256>>>(out, bpred);
    readout_kernel<<<nodeWarpBlocks, 256>>>(gid, out);
}

// round 8
// speedup vs baseline: 1.9273x; 1.0945x over previous
#include <cuda_runtime.h>
#include <cuda_bf16.h>
#include <mma.h>

using namespace nvcuda;

// D-MPNN on GB300. Round 8: double-buffered A smem, one barrier per tile,
// gather LDGs overlapped with MMA. Init uses bias-row trick (A col 134 = 1,
// W row 134 = bias) to fit 2 CTAs/SM with double buffering.

#define NN 200000
#define NE 800000
#define HD 128
#define NGB 2000
#define SCANB 512
#define NSCAN ((NN + SCANB - 1) / SCANB)

__device__ float g_x[(size_t)NN * HD];
__device__ float g_he[(size_t)NE * HD];
__device__ float g_agg[(size_t)NN * HD];
__device__ float g_wrp[HD];
__device__ int g_deg[NN];
__device__ int g_off[NN];
__device__ int g_cursor[NN];
__device__ int g_csr[NE];
__device__ int g_bsum[NSCAN];

__device__ __forceinline__ __nv_bfloat162 pack_hi(float a, float b) {
    return __nv_bfloat162(__float2bfloat16_rn(a), __float2bfloat16_rn(b));
}
__device__ __forceinline__ __nv_bfloat162 pack_lo(float a, float b, __nv_bfloat162 hi) {
    return __nv_bfloat162(__float2bfloat16_rn(a - __bfloat162float(hi.x)),
                          __float2bfloat16_rn(b - __bfloat162float(hi.y)));
}

// ---------------------------------------------------------------- CSR build
__global__ void zero_deg_kernel() {
    int i = blockIdx.x * blockDim.x + threadIdx.x;
    if (i < NN) g_deg[i] = 0;
}
__global__ void deg_count_kernel(const int* __restrict__ dst) {
    int k = blockIdx.x * blockDim.x + threadIdx.x;
    if (k < NE) atomicAdd(&g_deg[dst[k]], 1);
}
__global__ void scan_a_kernel() {
    __shared__ int s[SCANB];
    int t = threadIdx.x;
    int n = blockIdx.x * SCANB + t;
    s[t] = (n < NN) ? g_deg[n] : 0;
    __syncthreads();
    for (int o = SCANB / 2; o > 0; o >>= 1) {
        if (t < o) s[t] += s[t + o];
        __syncthreads();
    }
    if (t == 0) g_bsum[blockIdx.x] = s[0];
}
__global__ void scan_b_kernel() {
    if (threadIdx.x == 0) {
        int run = 0;
        for (int b = 0; b < NSCAN; ++b) { int v = g_bsum[b]; g_bsum[b] = run; run += v; }
    }
}
__global__ void scan_c_kernel() {
    __shared__ int s[SCANB];
    int t = threadIdx.x;
    int n = blockIdx.x * SCANB + t;
    int val = (n < NN) ? g_deg[n] : 0;
    s[t] = val;
    __syncthreads();
    for (int o = 1; o < SCANB; o <<= 1) {
        int x = (t >= o) ? s[t - o] : 0;
        __syncthreads();
        s[t] += x;
        __syncthreads();
    }
    if (n < NN) {
        int off = g_bsum[blockIdx.x] + s[t] - val;
        g_off[n] = off;
        g_cursor[n] = off;
    }
}
__global__ void csr_fill_kernel(const int* __restrict__ dst) {
    int k = blockIdx.x * blockDim.x + threadIdx.x;
    if (k < NE) {
        int pos = atomicAdd(&g_cursor[dst[k]], 1);
        g_csr[pos] = k;
    }
}

// ---------------------------------------------------------------- embed
__global__ void __launch_bounds__(128) embed_kernel(
    const float* __restrict__ h, const float* __restrict__ Wemb)
{
    __shared__ float sh[64 * 28];
    int n0 = blockIdx.x * 64;
    int tid = threadIdx.x;
    for (int idx = tid; idx < 64 * 28; idx += 128)
        sh[idx] = h[(size_t)n0 * 28 + idx];
    __syncthreads();
    float w[28];
#pragma unroll
    for (int i = 0; i < 28; ++i) w[i] = Wemb[i * HD + tid];
    for (int n = 0; n < 64; ++n) {
        float acc = 0.f;
#pragma unroll
        for (int i = 0; i < 28; ++i) acc += sh[n * 28 + i] * w[i];
        g_x[(size_t)(n0 + n) * HD + tid] = acc;
    }
}

// ---------------------------------------------------------------- layer GEMM
// TE=32, double-buffered A, 2 CTAs/SM, warp tile 32x16.
#define LTE 32
#define LNT (NE / LTE)   // 25000
#define LW_SZ  (128 * 136)              // halves per W array
#define LA_SZ  (LTE * 136)              // halves per A array per buffer
// layout: Whi | Wlo | bias(16x128 f32) | A0hi | A0lo | A1hi | A1lo
#define SMEM_LAYER (2 * LW_SZ * 2 + 16 * 128 * 4 + 4 * LA_SZ * 2)   // 112,640

__global__ void __launch_bounds__(256, 2) layer_kernel(
    const float* __restrict__ W, const float* __restrict__ bias,
    const int* __restrict__ src)
{
    extern __shared__ char sm[];
    __nv_bfloat16* sWhi = (__nv_bfloat16*)sm;
    __nv_bfloat16* sWlo = sWhi + LW_SZ;
    float* sBias = (float*)(sWlo + LW_SZ);
    __nv_bfloat16* sA = (__nv_bfloat16*)(sBias + 16 * 128);   // 4 arrays of LA_SZ

    int tid = threadIdx.x;
    for (int i = tid; i < 128 * 128; i += 256) {
        int k = i >> 7, n = i & 127;
        float v = W[i];
        __nv_bfloat16 h = __float2bfloat16_rn(v);
        sWhi[k * 136 + n] = h;
        sWlo[k * 136 + n] = __float2bfloat16_rn(v - __bfloat162float(h));
    }
    for (int i = tid; i < 16 * 128; i += 256) sBias[i] = bias[i & 127];

    int w = tid >> 5;                // warp 0..7
    int cq = w * 16;                 // 16-col slice
    int r = tid >> 3;                // gather row 0..31
    int q = (tid & 7) * 16;          // gather col chunk

    // gather one tile into buffer b
    auto gather = [&](int t, int b) {
        int e0 = t * LTE;
        int s = __ldg(&src[e0 + r]);
        const float4* a = (const float4*)&g_agg[(size_t)s * HD + q];
        const float4* h = (const float4*)&g_he[(size_t)(e0 + (r ^ 1)) * HD + q];
        __nv_bfloat162* dh = (__nv_bfloat162*)&sA[(2 * b) * LA_SZ + r * 136 + q];
        __nv_bfloat162* dl = (__nv_bfloat162*)&sA[(2 * b + 1) * LA_SZ + r * 136 + q];
#pragma unroll
        for (int c = 0; c < 4; ++c) {
            float4 av = a[c]; float4 hv = h[c];
            float m0 = av.x - hv.x, m1 = av.y - hv.y;
            float m2 = av.z - hv.z, m3 = av.w - hv.w;
            __nv_bfloat162 h01 = pack_hi(m0, m1);
            __nv_bfloat162 h23 = pack_hi(m2, m3);
            dh[2 * c] = h01; dh[2 * c + 1] = h23;
            dl[2 * c] = pack_lo(m0, m1, h01);
            dl[2 * c + 1] = pack_lo(m2, m3, h23);
        }
    };

    int t = blockIdx.x;
    int buf = 0;
    __syncthreads();          // W/bias ready
    if (t < LNT) gather(t, 0);
    __syncthreads();

    for (; t < LNT; ) {
        int tn = t + gridDim.x;
        int e0 = t * LTE;

        if (tn < LNT) gather(tn, buf ^ 1);   // LDG+STS overlap MMA below

        // residual fragments (LDGs overlap MMA)
        float* base = &g_he[(size_t)e0 * HD + cq];
        wmma::fragment<wmma::accumulator, 16, 16, 16, float> hf[2], acc[2];
#pragma unroll
        for (int i = 0; i < 2; ++i) {
            wmma::load_matrix_sync(hf[i], base + (size_t)(16 * i) * HD, HD, wmma::mem_row_major);
            wmma::load_matrix_sync(acc[i], sBias + cq, 128, wmma::mem_row_major);
        }

        const __nv_bfloat16* Ahi = &sA[(2 * buf) * LA_SZ];
        const __nv_bfloat16* Alo = &sA[(2 * buf + 1) * LA_SZ];
#pragma unroll
        for (int kt = 0; kt < 8; ++kt) {
            wmma::fragment<wmma::matrix_a, 16, 16, 16, __nv_bfloat16, wmma::row_major> ahi[2], alo[2];
#pragma unroll
            for (int i = 0; i < 2; ++i) {
                wmma::load_matrix_sync(ahi[i], Ahi + (16 * i) * 136 + kt * 16, 136);
                wmma::load_matrix_sync(alo[i], Alo + (16 * i) * 136 + kt * 16, 136);
            }
            wmma::fragment<wmma::matrix_b, 16, 16, 16, __nv_bfloat16, wmma::row_major> bhi, blo;
            wmma::load_matrix_sync(bhi, sWhi + kt * 16 * 136 + cq, 136);
            wmma::load_matrix_sync(blo, sWlo + kt * 16 * 136 + cq, 136);
#pragma unroll
            for (int i = 0; i < 2; ++i) {
                wmma::mma_sync(acc[i], ahi[i], bhi, acc[i]);
                wmma::mma_sync(acc[i], alo[i], bhi, acc[i]);
                wmma::mma_sync(acc[i], ahi[i], blo, acc[i]);
            }
        }
        __syncthreads();   // all reads of buf done; next gather's buffer safe

        // epilogue: relu + residual
#pragma unroll
        for (int i = 0; i < 2; ++i) {
#pragma unroll
            for (int x = 0; x < acc[i].num_elements; ++x)
                acc[i].x[x] = fmaxf(acc[i].x[x], 0.f) + hf[i].x[x];
            wmma::store_matrix_sync(base + (size_t)(16 * i) * HD, acc[i], HD, wmma::mem_row_major);
        }
        t = tn; buf ^= 1;
    }
}

// ---------------------------------------------------------------- init GEMM
// TE=32, K=144 (cols 128-133 = e, col 134 = 1.0 -> bias row), double-buffered,
// W stores only 135 rows; kt=8 overread hits adjacent smem (finite bf16 * 0).
#define ITE 32
#define INT_ (NE / ITE)                 // 25000
#define IW_ROWS 135
#define IW_SZ (IW_ROWS * 136)           // halves per W array
#define IA_SZ (ITE * 152)               // halves per A array per buffer
// layout: Whi | Wlo | A0hi | A0lo | A1hi | A1lo   (W first: overreads stay in-bounds)
#define SMEM_INIT (2 * IW_SZ * 2 + 4 * IA_SZ * 2)   // 73,440 + 38,912 = 112,352

__global__ void __launch_bounds__(256, 2) init_kernel(
    const float* __restrict__ W, const float* __restrict__ bias,
    const float* __restrict__ eAttr, const int* __restrict__ src)
{
    extern __shared__ char sm[];
    __nv_bfloat16* sWhi = (__nv_bfloat16*)sm;
    __nv_bfloat16* sWlo = sWhi + IW_SZ;
    __nv_bfloat16* sA = sWlo + IW_SZ;

    int tid = threadIdx.x;
    for (int i = tid; i < IW_ROWS * 128; i += 256) {
        int k = i >> 7, n = i & 127;
        float v = (k < 134) ? W[k * 128 + n] : bias[n];   // row 134 = bias
        __nv_bfloat16 h = __float2bfloat16_rn(v);
        sWhi[k * 136 + n] = h;
        sWlo[k * 136 + n] = __float2bfloat16_rn(v - __bfloat162float(h));
    }

    int w = tid >> 5;
    int cq = w * 16;
    int r = tid >> 3;
    int q = (tid & 7) * 16;

    auto gather = [&](int t, int b) {
        int e0 = t * ITE;
        int s = __ldg(&src[e0 + r]);
        const float4* a = (const float4*)&g_x[(size_t)s * HD + q];
        __nv_bfloat162* dh = (__nv_bfloat162*)&sA[(2 * b) * IA_SZ + r * 152 + q];
        __nv_bfloat162* dl = (__nv_bfloat162*)&sA[(2 * b + 1) * IA_SZ + r * 152 + q];
#pragma unroll
        for (int c = 0; c < 4; ++c) {
            float4 v = a[c];
            __nv_bfloat162 h01 = pack_hi(v.x, v.y);
            __nv_bfloat162 h23 = pack_hi(v.z, v.w);
            dh[2 * c] = h01; dh[2 * c + 1] = h23;
            dl[2 * c] = pack_lo(v.x, v.y, h01);
            dl[2 * c + 1] = pack_lo(v.z, v.w, h23);
        }
        if ((tid & 7) == 0) {   // cols 128..151: e(6), 1.0 (bias row), zeros
            __nv_bfloat162* eh = (__nv_bfloat162*)&sA[(2 * b) * IA_SZ + r * 152 + 128];
            __nv_bfloat162* el = (__nv_bfloat162*)&sA[(2 * b + 1) * IA_SZ + r * 152 + 128];
            const float* ep = &eAttr[(size_t)(e0 + r) * 6];
#pragma unroll
            for (int c = 0; c < 12; ++c) {
                float a0 = (2 * c < 6) ? __ldg(ep + 2 * c) : (2 * c == 134 - 128 ? 1.f : 0.f);
                float a1 = (2 * c + 1 < 6) ? __ldg(ep + 2 * c + 1) : (2 * c + 1 == 134 - 128 ? 1.f : 0.f);
                __nv_bfloat162 hh = pack_hi(a0, a1);
                eh[c] = hh;
                el[c] = pack_lo(a0, a1, hh);
            }
        }
    };

    int t = blockIdx.x;
    int buf = 0;
    __syncthreads();
    if (t < INT_) gather(t, 0);
    __syncthreads();

    for (; t < INT_; ) {
        int tn = t + gridDim.x;
        int e0 = t * ITE;

        if (tn < INT_) gather(tn, buf ^ 1);

        wmma::fragment<wmma::accumulator, 16, 16, 16, float> acc[2];
#pragma unroll
        for (int i = 0; i < 2; ++i) wmma::fill_fragment(acc[i], 0.f);

        const __nv_bfloat16* Ahi = &sA[(2 * buf) * IA_SZ];
        const __nv_bfloat16* Alo = &sA[(2 * buf + 1) * IA_SZ];
#pragma unroll
        for (int kt = 0; kt < 9; ++kt) {
            wmma::fragment<wmma::matrix_a, 16, 16, 16, __nv_bfloat16, wmma::row_major> ahi[2], alo[2];
#pragma unroll
            for (int i = 0; i < 2; ++i) {
                wmma::load_matrix_sync(ahi[i], Ahi + (16 * i) * 152 + kt * 16, 152);
                wmma::load_matrix_sync(alo[i], Alo + (16 * i) * 152 + kt * 16, 152);
            }
            wmma::fragment<wmma::matrix_b, 16, 16, 16, __nv_bfloat16, wmma::row_major> bhi, blo;
            wmma::load_matrix_sync(bhi, sWhi + kt * 16 * 136 + cq, 136);
            wmma::load_matrix_sync(blo, sWlo + kt * 16 * 136 + cq, 136);
#pragma unroll
            for (int i = 0; i < 2; ++i) {
                wmma::mma_sync(acc[i], ahi[i], bhi, acc[i]);
                wmma::mma_sync(acc[i], alo[i], bhi, acc[i]);
                wmma::mma_sync(acc[i], ahi[i], blo, acc[i]);
            }
        }
        __syncthreads();

        float* base = &g_he[(size_t)e0 * HD + cq];
#pragma unroll
        for (int i = 0; i < 2; ++i) {
#pragma unroll
            for (int x = 0; x < acc[i].num_elements; ++x)
                acc[i].x[x] = fmaxf(acc[i].x[x], 0.f);
            wmma::store_matrix_sync(base + (size_t)(16 * i) * HD, acc[i], HD, wmma::mem_row_major);
        }
        t = tn; buf ^= 1;
    }
}

// ---------------------------------------------------------------- agg
__global__ void __launch_bounds__(256) agg_kernel() {
    int node = (blockIdx.x * blockDim.x + threadIdx.x) >> 5;
    int lane = threadIdx.x & 31;
    if (node >= NN) return;
    int start = g_off[node];
    int d = g_deg[node];
    float4 acc = make_float4(0.f, 0.f, 0.f, 0.f);
    for (int j = 0; j < d; ++j) {
        int e = g_csr[start + j];
        float4 v = reinterpret_cast<const float4*>(&g_he[(size_t)e * HD])[lane];
        acc.x += v.x; acc.y += v.y; acc.z += v.z; acc.w += v.w;
    }
    reinterpret_cast<float4*>(&g_agg[(size_t)node * HD])[lane] = acc;
}

// ---------------------------------------------------------------- wrp / outinit / readout
__global__ void wrp_kernel(const float* __restrict__ Wro, const float* __restrict__ Wpred) {
    __shared__ float sp[HD];
    int i = threadIdx.x;
    sp[i] = Wpred[i];
    __syncthreads();
    float a = 0.f;
    for (int j = 0; j < HD; ++j) a += Wro[(size_t)i * HD + j] * sp[j];
    g_wrp[i] = a;
}
__global__ void outinit_kernel(float* __restrict__ out, const float* __restrict__ bpred) {
    int i = blockIdx.x * blockDim.x + threadIdx.x;
    if (i < NGB) out[i] = bpred[0];
}
__global__ void __launch_bounds__(256) readout_kernel(
    const int* __restrict__ gid, float* __restrict__ out)
{
    int node = (blockIdx.x * blockDim.x + threadIdx.x) >> 5;
    int lane = threadIdx.x & 31;
    if (node >= NN) return;
    int start = g_off[node];
    int d = g_deg[node];
    float4 acc = make_float4(0.f, 0.f, 0.f, 0.f);
    for (int j = 0; j < d; ++j) {
        int e = g_csr[start + j];
        float4 v = reinterpret_cast<const float4*>(&g_he[(size_t)e * HD])[lane];
        acc.x += v.x; acc.y += v.y; acc.z += v.z; acc.w += v.w;
    }
    float4 w = reinterpret_cast<const float4*>(g_wrp)[lane];
    float s = acc.x * w.x + acc.y * w.y + acc.z * w.z + acc.w * w.w;
#pragma unroll
    for (int o = 16; o; o >>= 1) s += __shfl_xor_sync(0xFFFFFFFFu, s, o);
    if (lane == 0) atomicAdd(&out[gid[node]], s);
}

// ---------------------------------------------------------------- launch
extern "C" void kernel_launch(void* const* d_in, const int* in_sizes, int n_in,
                              void* d_out, int out_size)
{
    const float* h      = (const float*)d_in[0];
    const float* e      = (const float*)d_in[1];
    const float* Wemb   = (const float*)d_in[2];
    const float* Winit  = (const float*)d_in[3];
    const float* binit  = (const float*)d_in[4];
    const float* Wlay   = (const float*)d_in[5];
    const float* blay   = (const float*)d_in[6];
    const float* Wro    = (const float*)d_in[7];
    const float* Wpred  = (const float*)d_in[8];
    const float* bpred  = (const float*)d_in[9];
    const int*   src    = (const int*)d_in[10];
    const int*   dst    = (const int*)d_in[11];
    const int*   gid    = (const int*)d_in[12];
    float* out = (float*)d_out;

    cudaFuncSetAttribute(init_kernel,  cudaFuncAttributeMaxDynamicSharedMemorySize, SMEM_INIT);
    cudaFuncSetAttribute(layer_kernel, cudaFuncAttributeMaxDynamicSharedMemorySize, SMEM_LAYER);

    const int embedBlocks = NN / 64;
    const int nodeWarpBlocks = (NN * 32 + 255) / 256;

    // captured profile = launch index 3 -> init GEMM
    zero_deg_kernel<<<(NN + 255) / 256, 256>>>();                    // 0
    deg_count_kernel<<<(NE + 255) / 256, 256>>>(dst);                // 1
    embed_kernel<<<embedBlocks, 128>>>(h, Wemb);                     // 2
    init_kernel<<<296, 256, SMEM_INIT>>>(Winit, binit, e, src);      // 3 <- profiled
    scan_a_kernel<<<NSCAN, SCANB>>>();                               // 4
    scan_b_kernel<<<1, 32>>>();                                      // 5
    scan_c_kernel<<<NSCAN, SCANB>>>();                               // 6
    csr_fill_kernel<<<(NE + 255) / 256, 256>>>(dst);                 // 7

    for (int l = 0; l < 4; ++l) {
        agg_kernel<<<nodeWarpBlocks, 256>>>();
        layer_kernel<<<296, 256, SMEM_LAYER>>>(
            Wlay + (size_t)l * HD * HD, blay + (size_t)l * HD, src);
    }

    wrp_kernel<<<1, HD>>>(Wro, Wpred);
    outinit_kernel<<<(NGB + 255) / 256, 256>>>(out, bpred);
    readout_kernel<<<nodeWarpBlocks, 256>>>(gid, out);
}

// round 11
// speedup vs baseline: 1.9432x; 1.0082x over previous
#include <cuda_runtime.h>
#include <cuda_bf16.h>
#include <mma.h>
#include <cstdint>

using namespace nvcuda;

// D-MPNN on GB300. Round 11: layer GEMMs via explicit mma.sync.m16n8k16 with
// W cached in registers (loaded once per persistent block), A via ldmatrix.x4
// from a pad-136 smem tile (double-buffered), bf16 hi/lo 3-term numerics.
// Init = R8 wmma (proven). No tcgen05 (harness PTX target rejects it).

#define NN 200000
#define NE 800000
#define HD 128
#define NGB 2000
#define SCANB 512
#define NSCAN ((NN + SCANB - 1) / SCANB)

__device__ float g_x[(size_t)NN * HD];
__device__ float g_he[(size_t)NE * HD];
__device__ float g_agg[(size_t)NN * HD];
__device__ float g_wrp[HD];
__device__ int g_deg[NN];
__device__ int g_off[NN];
__device__ int g_cursor[NN];
__device__ int g_csr[NE];
__device__ int g_bsum[NSCAN];

__device__ __forceinline__ __nv_bfloat162 pack_hi(float a, float b) {
    return __nv_bfloat162(__float2bfloat16_rn(a), __float2bfloat16_rn(b));
}
__device__ __forceinline__ __nv_bfloat162 pack_lo(float a, float b, __nv_bfloat162 hi) {
    return __nv_bfloat162(__float2bfloat16_rn(a - __bfloat162float(hi.x)),
                          __float2bfloat16_rn(b - __bfloat162float(hi.y)));
}
__device__ __forceinline__ uint32_t b2u(__nv_bfloat162 v) {
    return *reinterpret_cast<uint32_t*>(&v);
}
__device__ __forceinline__ uint32_t smem_u32(const void* p) {
    uint32_t a;
    asm("{ .reg .u64 t; cvta.to.shared.u64 t, %1; cvt.u32.u64 %0, t; }" : "=r"(a) : "l"(p));
    return a;
}
__device__ __forceinline__ void ldsm_x4(uint32_t* r, uint32_t addr) {
    asm volatile("ldmatrix.sync.aligned.m8n8.x4.shared.b16 {%0,%1,%2,%3}, [%4];"
                 : "=r"(r[0]), "=r"(r[1]), "=r"(r[2]), "=r"(r[3]) : "r"(addr));
}
__device__ __forceinline__ void mma16816(float* d, const uint32_t* a, uint32_t b0, uint32_t b1) {
    asm volatile("mma.sync.aligned.m16n8k16.row.col.f32.bf16.bf16.f32 "
                 "{%0,%1,%2,%3},{%4,%5,%6,%7},{%8,%9},{%0,%1,%2,%3};"
                 : "+f"(d[0]), "+f"(d[1]), "+f"(d[2]), "+f"(d[3])
                 : "r"(a[0]), "r"(a[1]), "r"(a[2]), "r"(a[3]), "r"(b0), "r"(b1));
}

// ---------------------------------------------------------------- CSR build
__global__ void zero_deg_kernel() {
    int i = blockIdx.x * blockDim.x + threadIdx.x;
    if (i < NN) g_deg[i] = 0;
}
__global__ void deg_count_kernel(const int* __restrict__ dst) {
    int k = blockIdx.x * blockDim.x + threadIdx.x;
    if (k < NE) atomicAdd(&g_deg[dst[k]], 1);
}
__global__ void scan_a_kernel() {
    __shared__ int s[SCANB];
    int t = threadIdx.x;
    int n = blockIdx.x * SCANB + t;
    s[t] = (n < NN) ? g_deg[n] : 0;
    __syncthreads();
    for (int o = SCANB / 2; o > 0; o >>= 1) {
        if (t < o) s[t] += s[t + o];
        __syncthreads();
    }
    if (t == 0) g_bsum[blockIdx.x] = s[0];
}
__global__ void scan_b_kernel() {
    if (threadIdx.x == 0) {
        int run = 0;
        for (int b = 0; b < NSCAN; ++b) { int v = g_bsum[b]; g_bsum[b] = run; run += v; }
    }
}
__global__ void scan_c_kernel() {
    __shared__ int s[SCANB];
    int t = threadIdx.x;
    int n = blockIdx.x * SCANB + t;
    int val = (n < NN) ? g_deg[n] : 0;
    s[t] = val;
    __syncthreads();
    for (int o = 1; o < SCANB; o <<= 1) {
        int x = (t >= o) ? s[t - o] : 0;
        __syncthreads();
        s[t] += x;
        __syncthreads();
    }
    if (n < NN) {
        int off = g_bsum[blockIdx.x] + s[t] - val;
        g_off[n] = off;
        g_cursor[n] = off;
    }
}
__global__ void csr_fill_kernel(const int* __restrict__ dst) {
    int k = blockIdx.x * blockDim.x + threadIdx.x;
    if (k < NE) {
        int pos = atomicAdd(&g_cursor[dst[k]], 1);
        g_csr[pos] = k;
    }
}

// ---------------------------------------------------------------- embed
__global__ void __launch_bounds__(128) embed_kernel(
    const float* __restrict__ h, const float* __restrict__ Wemb)
{
    __shared__ float sh[64 * 28];
    int n0 = blockIdx.x * 64;
    int tid = threadIdx.x;
    for (int idx = tid; idx < 64 * 28; idx += 128)
        sh[idx] = h[(size_t)n0 * 28 + idx];
    __syncthreads();
    float w[28];
#pragma unroll
    for (int i = 0; i < 28; ++i) w[i] = Wemb[i * HD + tid];
    for (int n = 0; n < 64; ++n) {
        float acc = 0.f;
#pragma unroll
        for (int i = 0; i < 28; ++i) acc += sh[n * 28 + i] * w[i];
        g_x[(size_t)(n0 + n) * HD + tid] = acc;
    }
}

// ---------------------------------------------------------------- layer GEMM (mma.sync)
// TE=32 tile. A (hi/lo) double-buffered in smem (stride 136, ldmatrix-friendly).
// W cached per-warp in registers as col-major b-fragments: warp w owns cols
// [16w, 16w+16), Bh/Bl[kt][n8][half]. acc 32x16 per warp. 3 MMAs per product.
#define LTE 32
#define LNT (NE / LTE)                  // 25000
#define LA_SZ (LTE * 136)               // halves per A component
#define SMEM_LAYER (4 * LA_SZ * 2)      // 34,816 B

__global__ void __launch_bounds__(256, 2) layer_kernel(
    const float* __restrict__ W, const float* __restrict__ bias,
    const int* __restrict__ src)
{
    extern __shared__ char sm[];
    __nv_bfloat16* sA = (__nv_bfloat16*)sm;
    uint32_t sA_u32 = smem_u32(sA);

    int tid = threadIdx.x;
    int w = tid >> 5, l = tid & 31;
    int ncb = w * 16;

    // ---- W into registers (once per block) ----
    uint32_t Bh[8][2][2], Bl[8][2][2];
    {
        int kq = (l & 3) * 2;
        int nn = l >> 2;
#pragma unroll
        for (int kt = 0; kt < 8; ++kt)
#pragma unroll
            for (int j = 0; j < 2; ++j) {
                int n = ncb + j * 8 + nn;
#pragma unroll
                for (int hhf = 0; hhf < 2; ++hhf) {
                    int k0 = kt * 16 + hhf * 8 + kq;
                    float w0 = __ldg(&W[k0 * 128 + n]);
                    float w1 = __ldg(&W[(k0 + 1) * 128 + n]);
                    __nv_bfloat162 hi = pack_hi(w0, w1);
                    Bh[kt][j][hhf] = b2u(hi);
                    Bl[kt][j][hhf] = b2u(pack_lo(w0, w1, hi));
                }
            }
    }
    // ---- bias regs (epilogue cols) ----
    float bs[2][2];
    {
        int ncl = (l & 3) * 2;
#pragma unroll
        for (int j = 0; j < 2; ++j) {
            bs[j][0] = __ldg(&bias[ncb + j * 8 + ncl]);
            bs[j][1] = __ldg(&bias[ncb + j * 8 + ncl + 1]);
        }
    }

    // ldmatrix per-lane source row/col within a 16x16 A tile
    int quad = l >> 3;
    int arow = (l & 7) + ((quad & 1) ? 8 : 0);
    int acol = (quad >= 2) ? 8 : 0;
    // gather indexing
    int gr = tid >> 3;              // row 0..31
    int gq = (tid & 7) * 16;        // col chunk

    auto gather = [&](int t, int b) {
        int e0 = t * LTE;
        int s = __ldg(&src[e0 + gr]);
        const float4* a = (const float4*)&g_agg[(size_t)s * HD + gq];
        const float4* h = (const float4*)&g_he[(size_t)(e0 + (gr ^ 1)) * HD + gq];
        __nv_bfloat162* dh = (__nv_bfloat162*)&sA[(2 * b) * LA_SZ + gr * 136 + gq];
        __nv_bfloat162* dl = (__nv_bfloat162*)&sA[(2 * b + 1) * LA_SZ + gr * 136 + gq];
#pragma unroll
        for (int c = 0; c < 4; ++c) {
            float4 av = a[c]; float4 hv = h[c];
            float m0 = av.x - hv.x, m1 = av.y - hv.y;
            float m2 = av.z - hv.z, m3 = av.w - hv.w;
            __nv_bfloat162 h01 = pack_hi(m0, m1);
            __nv_bfloat162 h23 = pack_hi(m2, m3);
            dh[2 * c] = h01; dh[2 * c + 1] = h23;
            dl[2 * c] = pack_lo(m0, m1, h01);
            dl[2 * c + 1] = pack_lo(m2, m3, h23);
        }
    };

    int t = blockIdx.x;
    int buf = 0;
    if (t < LNT) gather(t, 0);
    __syncthreads();

    for (; t < LNT; ) {
        int tn = t + gridDim.x;
        int e0 = t * LTE;

        if (tn < LNT) gather(tn, buf ^ 1);   // overlaps MMA below

        float acc[2][2][4];
#pragma unroll
        for (int i = 0; i < 2; ++i)
#pragma unroll
            for (int j = 0; j < 2; ++j)
#pragma unroll
                for (int x = 0; x < 4; ++x) acc[i][j][x] = 0.f;

        uint32_t baseH = sA_u32 + (2 * buf) * LA_SZ * 2;
        uint32_t baseL = sA_u32 + (2 * buf + 1) * LA_SZ * 2;
#pragma unroll
        for (int kt = 0; kt < 8; ++kt) {
#pragma unroll
            for (int i = 0; i < 2; ++i) {
                uint32_t ah[4], al[4];
                uint32_t off = (uint32_t)(((i * 16 + arow) * 136 + kt * 16 + acol) * 2);
                ldsm_x4(ah, baseH + off);
                ldsm_x4(al, baseL + off);
#pragma unroll
                for (int j = 0; j < 2; ++j) {
                    mma16816(acc[i][j], ah, Bh[kt][j][0], Bh[kt][j][1]);
                    mma16816(acc[i][j], al, Bh[kt][j][0], Bh[kt][j][1]);
                    mma16816(acc[i][j], ah, Bl[kt][j][0], Bl[kt][j][1]);
                }
            }
        }
        __syncthreads();   // reads of buf done; next gather may overwrite

        // epilogue: relu(acc + bias) + he residual
        int grow = l >> 2, ncl = (l & 3) * 2;
#pragma unroll
        for (int i = 0; i < 2; ++i) {
            int r0 = e0 + i * 16 + grow;
#pragma unroll
            for (int j = 0; j < 2; ++j) {
                int c = ncb + j * 8 + ncl;
                float2* p0 = (float2*)&g_he[(size_t)r0 * HD + c];
                float2* p1 = (float2*)&g_he[(size_t)(r0 + 8) * HD + c];
                float2 h0 = *p0, h1 = *p1;
                float2 o0, o1;
                o0.x = fmaxf(acc[i][j][0] + bs[j][0], 0.f) + h0.x;
                o0.y = fmaxf(acc[i][j][1] + bs[j][1], 0.f) + h0.y;
                o1.x = fmaxf(acc[i][j][2] + bs[j][0], 0.f) + h1.x;
                o1.y = fmaxf(acc[i][j][3] + bs[j][1], 0.f) + h1.y;
                *p0 = o0; *p1 = o1;
            }
        }
        t = tn; buf ^= 1;
    }
}

// ---------------------------------------------------------------- init GEMM (R8 wmma, proven)
#define ITE 32
#define INT_ (NE / ITE)
#define IW_ROWS 135
#define IW_SZ (IW_ROWS * 136)
#define IA_SZ (ITE * 152)
#define SMEM_INIT (2 * IW_SZ * 2 + 4 * IA_SZ * 2)

__global__ void __launch_bounds__(256, 2) init_kernel(
    const float* __restrict__ W, const float* __restrict__ bias,
    const float* __restrict__ eAttr, const int* __restrict__ src)
{
    extern __shared__ char sm[];
    __nv_bfloat16* sWhi = (__nv_bfloat16*)sm;
    __nv_bfloat16* sWlo = sWhi + IW_SZ;
    __nv_bfloat16* sA = sWlo + IW_SZ;

    int tid = threadIdx.x;
    for (int i = tid; i < IW_ROWS * 128; i += 256) {
        int k = i >> 7, n = i & 127;
        float v = (k < 134) ? W[k * 128 + n] : bias[n];
        __nv_bfloat16 hb = __float2bfloat16_rn(v);
        sWhi[k * 136 + n] = hb;
        sWlo[k * 136 + n] = __float2bfloat16_rn(v - __bfloat162float(hb));
    }

    int w = tid >> 5;
    int cq = w * 16;
    int r = tid >> 3;
    int q = (tid & 7) * 16;

    auto gather = [&](int t, int b) {
        int e0 = t * ITE;
        int s = __ldg(&src[e0 + r]);
        const float4* a = (const float4*)&g_x[(size_t)s * HD + q];
        __nv_bfloat162* dh = (__nv_bfloat162*)&sA[(2 * b) * IA_SZ + r * 152 + q];
        __nv_bfloat162* dl = (__nv_bfloat162*)&sA[(2 * b + 1) * IA_SZ + r * 152 + q];
#pragma unroll
        for (int c = 0; c < 4; ++c) {
            float4 v = a[c];
            __nv_bfloat162 h01 = pack_hi(v.x, v.y);
            __nv_bfloat162 h23 = pack_hi(v.z, v.w);
            dh[2 * c] = h01; dh[2 * c + 1] = h23;
            dl[2 * c] = pack_lo(v.x, v.y, h01);
            dl[2 * c + 1] = pack_lo(v.z, v.w, h23);
        }
        if ((tid & 7) == 0) {   // cols 128..151: e(6), col 134 = 1 (bias), zeros
            __nv_bfloat162* eh = (__nv_bfloat162*)&sA[(2 * b) * IA_SZ + r * 152 + 128];
            __nv_bfloat162* el = (__nv_bfloat162*)&sA[(2 * b + 1) * IA_SZ + r * 152 + 128];
            const float* ep = &eAttr[(size_t)(e0 + r) * 6];
#pragma unroll
            for (int c = 0; c < 12; ++c) {
                float a0 = (2 * c < 6) ? __ldg(ep + 2 * c) : (2 * c == 6 ? 1.f : 0.f);
                float a1 = (2 * c + 1 < 6) ? __ldg(ep + 2 * c + 1) : 0.f;
                __nv_bfloat162 hh = pack_hi(a0, a1);
                eh[c] = hh;
                el[c] = pack_lo(a0, a1, hh);
            }
        }
    };

    int t = blockIdx.x;
    int buf = 0;
    __syncthreads();
    if (t < INT_) gather(t, 0);
    __syncthreads();

    for (; t < INT_; ) {
        int tn = t + gridDim.x;
        int e0 = t * ITE;
        if (tn < INT_) gather(tn, buf ^ 1);

        wmma::fragment<wmma::accumulator, 16, 16, 16, float> acc[2];
#pragma unroll
        for (int i = 0; i < 2; ++i) wmma::fill_fragment(acc[i], 0.f);

        const __nv_bfloat16* Ahi = &sA[(2 * buf) * IA_SZ];
        const __nv_bfloat16* Alo = &sA[(2 * buf + 1) * IA_SZ];
#pragma unroll
        for (int kt = 0; kt < 9; ++kt) {
            wmma::fragment<wmma::matrix_a, 16, 16, 16, __nv_bfloat16, wmma::row_major> ahi[2], alo[2];
#pragma unroll
            for (int i = 0; i < 2; ++i) {
                wmma::load_matrix_sync(ahi[i], Ahi + (16 * i) * 152 + kt * 16, 152);
                wmma::load_matrix_sync(alo[i], Alo + (16 * i) * 152 + kt * 16, 152);
            }
            wmma::fragment<wmma::matrix_b, 16, 16, 16, __nv_bfloat16, wmma::row_major> bhi, blo;
            wmma::load_matrix_sync(bhi, sWhi + kt * 16 * 136 + cq, 136);
            wmma::load_matrix_sync(blo, sWlo + kt * 16 * 136 + cq, 136);
#pragma unroll
            for (int i = 0; i < 2; ++i) {
                wmma::mma_sync(acc[i], ahi[i], bhi, acc[i]);
                wmma::mma_sync(acc[i], alo[i], bhi, acc[i]);
                wmma::mma_sync(acc[i], ahi[i], blo, acc[i]);
            }
        }
        __syncthreads();

        float* base = &g_he[(size_t)e0 * HD + cq];
#pragma unroll
        for (int i = 0; i < 2; ++i) {
#pragma unroll
            for (int x = 0; x < acc[i].num_elements; ++x)
                acc[i].x[x] = fmaxf(acc[i].x[x], 0.f);
            wmma::store_matrix_sync(base + (size_t)(16 * i) * HD, acc[i], HD, wmma::mem_row_major);
        }
        t = tn; buf ^= 1;
    }
}

// ---------------------------------------------------------------- agg
__global__ void __launch_bounds__(256) agg_kernel() {
    int node = (blockIdx.x * blockDim.x + threadIdx.x) >> 5;
    int lane = threadIdx.x & 31;
    if (node >= NN) return;
    int start = g_off[node];
    int d = g_deg[node];
    float4 acc = make_float4(0.f, 0.f, 0.f, 0.f);
    for (int j = 0; j < d; ++j) {
        int e = g_csr[start + j];
        float4 v = reinterpret_cast<const float4*>(&g_he[(size_t)e * HD])[lane];
        acc.x += v.x; acc.y += v.y; acc.z += v.z; acc.w += v.w;
    }
    reinterpret_cast<float4*>(&g_agg[(size_t)node * HD])[lane] = acc;
}

// ---------------------------------------------------------------- wrp / outinit / readout
__global__ void wrp_kernel(const float* __restrict__ Wro, const float* __restrict__ Wpred) {
    __shared__ float sp[HD];
    int i = threadIdx.x;
    sp[i] = Wpred[i];
    __syncthreads();
    float a = 0.f;
    for (int j = 0; j < HD; ++j) a += Wro[(size_t)i * HD + j] * sp[j];
    g_wrp[i] = a;
}
__global__ void outinit_kernel(float* __restrict__ out, const float* __restrict__ bpred) {
    int i = blockIdx.x * blockDim.x + threadIdx.x;
    if (i < NGB) out[i] = bpred[0];
}
__global__ void __launch_bounds__(256) readout_kernel(
    const int* __restrict__ gid, float* __restrict__ out)
{
    int node = (blockIdx.x * blockDim.x + threadIdx.x) >> 5;
    int lane = threadIdx.x & 31;
    if (node >= NN) return;
    int start = g_off[node];
    int d = g_deg[node];
    float4 acc = make_float4(0.f, 0.f, 0.f, 0.f);
    for (int j = 0; j < d; ++j) {
        int e = g_csr[start + j];
        float4 v = reinterpret_cast<const float4*>(&g_he[(size_t)e * HD])[lane];
        acc.x += v.x; acc.y += v.y; acc.z += v.z; acc.w += v.w;
    }
    float4 w = reinterpret_cast<const float4*>(g_wrp)[lane];
    float s = acc.x * w.x + acc.y * w.y + acc.z * w.z + acc.w * w.w;
#pragma unroll
    for (int o = 16; o; o >>= 1) s += __shfl_xor_sync(0xFFFFFFFFu, s, o);
    if (lane == 0) atomicAdd(&out[gid[node]], s);
}

// ---------------------------------------------------------------- launch
extern "C" void kernel_launch(void* const* d_in, const int* in_sizes, int n_in,
                              void* d_out, int out_size)
{
    const float* h      = (const float*)d_in[0];
    const float* e      = (const float*)d_in[1];
    const float* Wemb   = (const float*)d_in[2];
    const float* Winit  = (const float*)d_in[3];
    const float* binit  = (const float*)d_in[4];
    const float* Wlay   = (const float*)d_in[5];
    const float* blay   = (const float*)d_in[6];
    const float* Wro    = (const float*)d_in[7];
    const float* Wpred  = (const float*)d_in[8];
    const float* bpred  = (const float*)d_in[9];
    const int*   src    = (const int*)d_in[10];
    const int*   dst    = (const int*)d_in[11];
    const int*   gid    = (const int*)d_in[12];
    float* out = (float*)d_out;

    cudaFuncSetAttribute(init_kernel,  cudaFuncAttributeMaxDynamicSharedMemorySize, SMEM_INIT);
    cudaFuncSetAttribute(layer_kernel, cudaFuncAttributeMaxDynamicSharedMemorySize, SMEM_LAYER);

    const int embedBlocks = NN / 64;
    const int nodeWarpBlocks = (NN * 32 + 255) / 256;

    // captured profile = launch index 3 -> init GEMM
    zero_deg_kernel<<<(NN + 255) / 256, 256>>>();                    // 0
    deg_count_kernel<<<(NE + 255) / 256, 256>>>(dst);                // 1
    embed_kernel<<<embedBlocks, 128>>>(h, Wemb);                     // 2
    init_kernel<<<296, 256, SMEM_INIT>>>(Winit, binit, e, src);      // 3 <- profiled
    scan_a_kernel<<<NSCAN, SCANB>>>();                               // 4
    scan_b_kernel<<<1, 32>>>();                                      // 5
    scan_c_kernel<<<NSCAN, SCANB>>>();                               // 6
    csr_fill_kernel<<<(NE + 255) / 256, 256>>>(dst);                 // 7

    for (int l = 0; l < 4; ++l) {
        agg_kernel<<<nodeWarpBlocks, 256>>>();
        layer_kernel<<<296, 256, SMEM_LAYER>>>(
            Wlay + (size_t)l * HD * HD, blay + (size_t)l * HD, src);
    }

    wrp_kernel<<<1, HD>>>(Wro, Wpred);
    outinit_kernel<<<(NGB + 255) / 256, 256>>>(out, bpred);
    readout_kernel<<<nodeWarpBlocks, 256>>>(gid, out);
}

// round 12
// speedup vs baseline: 2.0876x; 1.0743x over previous
#include <cuda_runtime.h>
#include <cuda_bf16.h>
#include <mma.h>
#include <cstdint>

using namespace nvcuda;

// D-MPNN on GB300. Round 12: init GEMM eliminated algebraically
// (Wf = W_emb@W1 -> Z = h@Wf + b per node -> he0 = relu(Z[src] + e@W2)),
// MLP-4 CSR gathers in agg/readout, parallel scan_b.
// Layer GEMMs = R11 (mma.sync, register-W, TE=32, proven).

#define NN 200000
#define NE 800000
#define HD 128
#define NGB 2000
#define SCANB 512
#define NSCAN ((NN + SCANB - 1) / SCANB)

__device__ float g_x[(size_t)NN * HD];          // Z = h@Wf + b
__device__ float g_he[(size_t)NE * HD];
__device__ float g_agg[(size_t)NN * HD];
__device__ float g_wrp[HD];
__device__ float g_wf[28 * HD];                 // W_emb @ W_init[:128]
__device__ int g_deg[NN];
__device__ int g_off[NN];
__device__ int g_cursor[NN];
__device__ int g_csr[NE];
__device__ int g_bsum[NSCAN];

__device__ __forceinline__ __nv_bfloat162 pack_hi(float a, float b) {
    return __nv_bfloat162(__float2bfloat16_rn(a), __float2bfloat16_rn(b));
}
__device__ __forceinline__ __nv_bfloat162 pack_lo(float a, float b, __nv_bfloat162 hi) {
    return __nv_bfloat162(__float2bfloat16_rn(a - __bfloat162float(hi.x)),
                          __float2bfloat16_rn(b - __bfloat162float(hi.y)));
}
__device__ __forceinline__ uint32_t b2u(__nv_bfloat162 v) {
    return *reinterpret_cast<uint32_t*>(&v);
}
__device__ __forceinline__ uint32_t smem_u32(const void* p) {
    uint32_t a;
    asm("{ .reg .u64 t; cvta.to.shared.u64 t, %1; cvt.u32.u64 %0, t; }" : "=r"(a) : "l"(p));
    return a;
}
__device__ __forceinline__ void ldsm_x4(uint32_t* r, uint32_t addr) {
    asm volatile("ldmatrix.sync.aligned.m8n8.x4.shared.b16 {%0,%1,%2,%3}, [%4];"
                 : "=r"(r[0]), "=r"(r[1]), "=r"(r[2]), "=r"(r[3]) : "r"(addr));
}
__device__ __forceinline__ void mma16816(float* d, const uint32_t* a, uint32_t b0, uint32_t b1) {
    asm volatile("mma.sync.aligned.m16n8k16.row.col.f32.bf16.bf16.f32 "
                 "{%0,%1,%2,%3},{%4,%5,%6,%7},{%8,%9},{%0,%1,%2,%3};"
                 : "+f"(d[0]), "+f"(d[1]), "+f"(d[2]), "+f"(d[3])
                 : "r"(a[0]), "r"(a[1]), "r"(a[2]), "r"(a[3]), "r"(b0), "r"(b1));
}

// ---------------------------------------------------------------- CSR build
__global__ void zero_deg_kernel() {
    int i = blockIdx.x * blockDim.x + threadIdx.x;
    if (i < NN) g_deg[i] = 0;
}
__global__ void deg_count_kernel(const int* __restrict__ dst) {
    int k = blockIdx.x * blockDim.x + threadIdx.x;
    if (k < NE) atomicAdd(&g_deg[dst[k]], 1);
}
__global__ void scan_a_kernel() {
    __shared__ int s[SCANB];
    int t = threadIdx.x;
    int n = blockIdx.x * SCANB + t;
    s[t] = (n < NN) ? g_deg[n] : 0;
    __syncthreads();
    for (int o = SCANB / 2; o > 0; o >>= 1) {
        if (t < o) s[t] += s[t + o];
        __syncthreads();
    }
    if (t == 0) g_bsum[blockIdx.x] = s[0];
}
// parallel exclusive scan over NSCAN block sums (single block)
__global__ void scan_b_kernel() {
    __shared__ int s[512];
    int t = threadIdx.x;
    int v = (t < NSCAN) ? g_bsum[t] : 0;
    s[t] = v;
    __syncthreads();
    for (int o = 1; o < 512; o <<= 1) {
        int x = (t >= o) ? s[t - o] : 0;
        __syncthreads();
        s[t] += x;
        __syncthreads();
    }
    if (t < NSCAN) g_bsum[t] = s[t] - v;
}
__global__ void scan_c_kernel() {
    __shared__ int s[SCANB];
    int t = threadIdx.x;
    int n = blockIdx.x * SCANB + t;
    int val = (n < NN) ? g_deg[n] : 0;
    s[t] = val;
    __syncthreads();
    for (int o = 1; o < SCANB; o <<= 1) {
        int x = (t >= o) ? s[t - o] : 0;
        __syncthreads();
        s[t] += x;
        __syncthreads();
    }
    if (n < NN) {
        int off = g_bsum[blockIdx.x] + s[t] - val;
        g_off[n] = off;
        g_cursor[n] = off;
    }
}
__global__ void csr_fill_kernel(const int* __restrict__ dst) {
    int k = blockIdx.x * blockDim.x + threadIdx.x;
    if (k < NE) {
        int pos = atomicAdd(&g_cursor[dst[k]], 1);
        g_csr[pos] = k;
    }
}

// ---------------------------------------------------------------- Wf = W_emb @ W_init[:128]
__global__ void __launch_bounds__(128) wfuse_kernel(
    const float* __restrict__ Wemb, const float* __restrict__ Winit)
{
    __shared__ float sWe[28 * 128];
    int n = threadIdx.x;
    for (int i = n; i < 28 * 128; i += 128) sWe[i] = Wemb[i];
    __syncthreads();
    float acc[28];
#pragma unroll
    for (int a = 0; a < 28; ++a) acc[a] = 0.f;
    for (int k = 0; k < 128; ++k) {
        float wv = Winit[k * 128 + n];
#pragma unroll
        for (int a = 0; a < 28; ++a) acc[a] += sWe[a * 128 + k] * wv;
    }
#pragma unroll
    for (int a = 0; a < 28; ++a) g_wf[a * 128 + n] = acc[a];
}

// ---------------------------------------------------------------- Z = h @ Wf + b
__global__ void __launch_bounds__(128) z_kernel(
    const float* __restrict__ h, const float* __restrict__ binit)
{
    __shared__ float sh[64 * 28];
    int n0 = blockIdx.x * 64;
    int tid = threadIdx.x;
    for (int idx = tid; idx < 64 * 28; idx += 128)
        sh[idx] = h[(size_t)n0 * 28 + idx];
    __syncthreads();
    float w[28];
#pragma unroll
    for (int i = 0; i < 28; ++i) w[i] = g_wf[i * HD + tid];
    float b = binit[tid];
    for (int n = 0; n < 64; ++n) {
        float acc = b;
#pragma unroll
        for (int i = 0; i < 28; ++i) acc += sh[n * 28 + i] * w[i];
        g_x[(size_t)(n0 + n) * HD + tid] = acc;
    }
}

// ---------------------------------------------------------------- he0 = relu(Z[src] + e@W2)
// 8 edges per block (warp per edge), W2 = W_init rows 128..133 in smem.
__global__ void __launch_bounds__(256) init_combine_kernel(
    const float* __restrict__ Winit, const float* __restrict__ eAttr,
    const int* __restrict__ src)
{
    __shared__ float sW2[6 * 128];
    int tid = threadIdx.x;
    for (int i = tid; i < 6 * 128; i += 256) sW2[i] = Winit[128 * 128 + i];
    __syncthreads();

    int k = blockIdx.x * 8 + (tid >> 5);
    int lane = tid & 31;
    int s = __ldg(&src[k]);
    float ev[6];
#pragma unroll
    for (int j = 0; j < 6; ++j) ev[j] = __ldg(&eAttr[(size_t)k * 6 + j]);
    float4 z = *(const float4*)&g_x[(size_t)s * HD + lane * 4];
#pragma unroll
    for (int j = 0; j < 6; ++j) {
        float4 w2 = *(const float4*)&sW2[j * 128 + lane * 4];
        z.x += ev[j] * w2.x; z.y += ev[j] * w2.y;
        z.z += ev[j] * w2.z; z.w += ev[j] * w2.w;
    }
    z.x = fmaxf(z.x, 0.f); z.y = fmaxf(z.y, 0.f);
    z.z = fmaxf(z.z, 0.f); z.w = fmaxf(z.w, 0.f);
    *(float4*)&g_he[(size_t)k * HD + lane * 4] = z;
}

// ---------------------------------------------------------------- layer GEMM (R11, proven)
#define LTE 32
#define LNT (NE / LTE)
#define LA_SZ (LTE * 136)
#define SMEM_LAYER (4 * LA_SZ * 2)

__global__ void __launch_bounds__(256, 2) layer_kernel(
    const float* __restrict__ W, const float* __restrict__ bias,
    const int* __restrict__ src)
{
    extern __shared__ char sm[];
    __nv_bfloat16* sA = (__nv_bfloat16*)sm;
    uint32_t sA_u32 = smem_u32(sA);

    int tid = threadIdx.x;
    int w = tid >> 5, l = tid & 31;
    int ncb = w * 16;

    uint32_t Bh[8][2][2], Bl[8][2][2];
    {
        int kq = (l & 3) * 2;
        int nn = l >> 2;
#pragma unroll
        for (int kt = 0; kt < 8; ++kt)
#pragma unroll
            for (int j = 0; j < 2; ++j) {
                int n = ncb + j * 8 + nn;
#pragma unroll
                for (int hhf = 0; hhf < 2; ++hhf) {
                    int k0 = kt * 16 + hhf * 8 + kq;
                    float w0 = __ldg(&W[k0 * 128 + n]);
                    float w1 = __ldg(&W[(k0 + 1) * 128 + n]);
                    __nv_bfloat162 hi = pack_hi(w0, w1);
                    Bh[kt][j][hhf] = b2u(hi);
                    Bl[kt][j][hhf] = b2u(pack_lo(w0, w1, hi));
                }
            }
    }
    float bs[2][2];
    {
        int ncl = (l & 3) * 2;
#pragma unroll
        for (int j = 0; j < 2; ++j) {
            bs[j][0] = __ldg(&bias[ncb + j * 8 + ncl]);
            bs[j][1] = __ldg(&bias[ncb + j * 8 + ncl + 1]);
        }
    }

    int quad = l >> 3;
    int arow = (l & 7) + ((quad & 1) ? 8 : 0);
    int acol = (quad >= 2) ? 8 : 0;
    int gr = tid >> 3;
    int gq = (tid & 7) * 16;

    auto gather = [&](int t, int b) {
        int e0 = t * LTE;
        int s = __ldg(&src[e0 + gr]);
        const float4* a = (const float4*)&g_agg[(size_t)s * HD + gq];
        const float4* h = (const float4*)&g_he[(size_t)(e0 + (gr ^ 1)) * HD + gq];
        __nv_bfloat162* dh = (__nv_bfloat162*)&sA[(2 * b) * LA_SZ + gr * 136 + gq];
        __nv_bfloat162* dl = (__nv_bfloat162*)&sA[(2 * b + 1) * LA_SZ + gr * 136 + gq];
#pragma unroll
        for (int c = 0; c < 4; ++c) {
            float4 av = a[c]; float4 hv = h[c];
            float m0 = av.x - hv.x, m1 = av.y - hv.y;
            float m2 = av.z - hv.z, m3 = av.w - hv.w;
            __nv_bfloat162 h01 = pack_hi(m0, m1);
            __nv_bfloat162 h23 = pack_hi(m2, m3);
            dh[2 * c] = h01; dh[2 * c + 1] = h23;
            dl[2 * c] = pack_lo(m0, m1, h01);
            dl[2 * c + 1] = pack_lo(m2, m3, h23);
        }
    };

    int t = blockIdx.x;
    int buf = 0;
    if (t < LNT) gather(t, 0);
    __syncthreads();

    for (; t < LNT; ) {
        int tn = t + gridDim.x;
        int e0 = t * LTE;

        if (tn < LNT) gather(tn, buf ^ 1);

        float acc[2][2][4];
#pragma unroll
        for (int i = 0; i < 2; ++i)
#pragma unroll
            for (int j = 0; j < 2; ++j)
#pragma unroll
                for (int x = 0; x < 4; ++x) acc[i][j][x] = 0.f;

        uint32_t baseH = sA_u32 + (2 * buf) * LA_SZ * 2;
        uint32_t baseL = sA_u32 + (2 * buf + 1) * LA_SZ * 2;
#pragma unroll
        for (int kt = 0; kt < 8; ++kt) {
#pragma unroll
            for (int i = 0; i < 2; ++i) {
                uint32_t ah[4], al[4];
                uint32_t off = (uint32_t)(((i * 16 + arow) * 136 + kt * 16 + acol) * 2);
                ldsm_x4(ah, baseH + off);
                ldsm_x4(al, baseL + off);
#pragma unroll
                for (int j = 0; j < 2; ++j) {
                    mma16816(acc[i][j], ah, Bh[kt][j][0], Bh[kt][j][1]);
                    mma16816(acc[i][j], al, Bh[kt][j][0], Bh[kt][j][1]);
                    mma16816(acc[i][j], ah, Bl[kt][j][0], Bl[kt][j][1]);
                }
            }
        }
        __syncthreads();

        int grow = l >> 2, ncl = (l & 3) * 2;
#pragma unroll
        for (int i = 0; i < 2; ++i) {
            int r0 = e0 + i * 16 + grow;
#pragma unroll
            for (int j = 0; j < 2; ++j) {
                int c = ncb + j * 8 + ncl;
                float2* p0 = (float2*)&g_he[(size_t)r0 * HD + c];
                float2* p1 = (float2*)&g_he[(size_t)(r0 + 8) * HD + c];
                float2 h0 = *p0, h1 = *p1;
                float2 o0, o1;
                o0.x = fmaxf(acc[i][j][0] + bs[j][0], 0.f) + h0.x;
                o0.y = fmaxf(acc[i][j][1] + bs[j][1], 0.f) + h0.y;
                o1.x = fmaxf(acc[i][j][2] + bs[j][0], 0.f) + h1.x;
                o1.y = fmaxf(acc[i][j][3] + bs[j][1], 0.f) + h1.y;
                *p0 = o0; *p1 = o1;
            }
        }
        t = tn; buf ^= 1;
    }
}

// ---------------------------------------------------------------- agg (MLP-4 CSR gather)
__global__ void __launch_bounds__(256) agg_kernel() {
    int node = (blockIdx.x * blockDim.x + threadIdx.x) >> 5;
    int lane = threadIdx.x & 31;
    if (node >= NN) return;
    int start = __ldg(&g_off[node]);
    int d = __ldg(&g_deg[node]);
    float4 acc = make_float4(0.f, 0.f, 0.f, 0.f);
    int j = 0;
    for (; j + 4 <= d; j += 4) {
        int e0 = __ldg(&g_csr[start + j]);
        int e1 = __ldg(&g_csr[start + j + 1]);
        int e2 = __ldg(&g_csr[start + j + 2]);
        int e3 = __ldg(&g_csr[start + j + 3]);
        float4 v0 = ((const float4*)&g_he[(size_t)e0 * HD])[lane];
        float4 v1 = ((const float4*)&g_he[(size_t)e1 * HD])[lane];
        float4 v2 = ((const float4*)&g_he[(size_t)e2 * HD])[lane];
        float4 v3 = ((const float4*)&g_he[(size_t)e3 * HD])[lane];
        acc.x += v0.x + v1.x + v2.x + v3.x;
        acc.y += v0.y + v1.y + v2.y + v3.y;
        acc.z += v0.z + v1.z + v2.z + v3.z;
        acc.w += v0.w + v1.w + v2.w + v3.w;
    }
    for (; j < d; ++j) {
        int e = __ldg(&g_csr[start + j]);
        float4 v = ((const float4*)&g_he[(size_t)e * HD])[lane];
        acc.x += v.x; acc.y += v.y; acc.z += v.z; acc.w += v.w;
    }
    reinterpret_cast<float4*>(&g_agg[(size_t)node * HD])[lane] = acc;
}

// ---------------------------------------------------------------- wrp / outinit / readout
__global__ void wrp_kernel(const float* __restrict__ Wro, const float* __restrict__ Wpred) {
    __shared__ float sp[HD];
    int i = threadIdx.x;
    sp[i] = Wpred[i];
    __syncthreads();
    float a = 0.f;
    for (int j = 0; j < HD; ++j) a += Wro[(size_t)i * HD + j] * sp[j];
    g_wrp[i] = a;
}
__global__ void outinit_kernel(float* __restrict__ out, const float* __restrict__ bpred) {
    int i = blockIdx.x * blockDim.x + threadIdx.x;
    if (i < NGB) out[i] = bpred[0];
}
__global__ void __launch_bounds__(256) readout_kernel(
    const int* __restrict__ gid, float* __restrict__ out)
{
    int node = (blockIdx.x * blockDim.x + threadIdx.x) >> 5;
    int lane = threadIdx.x & 31;
    if (node >= NN) return;
    int start = __ldg(&g_off[node]);
    int d = __ldg(&g_deg[node]);
    float4 acc = make_float4(0.f, 0.f, 0.f, 0.f);
    int j = 0;
    for (; j + 4 <= d; j += 4) {
        int e0 = __ldg(&g_csr[start + j]);
        int e1 = __ldg(&g_csr[start + j + 1]);
        int e2 = __ldg(&g_csr[start + j + 2]);
        int e3 = __ldg(&g_csr[start + j + 3]);
        float4 v0 = ((const float4*)&g_he[(size_t)e0 * HD])[lane];
        float4 v1 = ((const float4*)&g_he[(size_t)e1 * HD])[lane];
        float4 v2 = ((const float4*)&g_he[(size_t)e2 * HD])[lane];
        float4 v3 = ((const float4*)&g_he[(size_t)e3 * HD])[lane];
        acc.x += v0.x + v1.x + v2.x + v3.x;
        acc.y += v0.y + v1.y + v2.y + v3.y;
        acc.z += v0.z + v1.z + v2.z + v3.z;
        acc.w += v0.w + v1.w + v2.w + v3.w;
    }
    for (; j < d; ++j) {
        int e = __ldg(&g_csr[start + j]);
        float4 v = ((const float4*)&g_he[(size_t)e * HD])[lane];
        acc.x += v.x; acc.y += v.y; acc.z += v.z; acc.w += v.w;
    }
    float4 w = reinterpret_cast<const float4*>(g_wrp)[lane];
    float s = acc.x * w.x + acc.y * w.y + acc.z * w.z + acc.w * w.w;
#pragma unroll
    for (int o = 16; o; o >>= 1) s += __shfl_xor_sync(0xFFFFFFFFu, s, o);
    if (lane == 0) atomicAdd(&out[gid[node]], s);
}

// ---------------------------------------------------------------- launch
extern "C" void kernel_launch(void* const* d_in, const int* in_sizes, int n_in,
                              void* d_out, int out_size)
{
    const float* h      = (const float*)d_in[0];
    const float* e      = (const float*)d_in[1];
    const float* Wemb   = (const float*)d_in[2];
    const float* Winit  = (const float*)d_in[3];
    const float* binit  = (const float*)d_in[4];
    const float* Wlay   = (const float*)d_in[5];
    const float* blay   = (const float*)d_in[6];
    const float* Wro    = (const float*)d_in[7];
    const float* Wpred  = (const float*)d_in[8];
    const float* bpred  = (const float*)d_in[9];
    const int*   src    = (const int*)d_in[10];
    const int*   dst    = (const int*)d_in[11];
    const int*   gid    = (const int*)d_in[12];
    float* out = (float*)d_out;

    cudaFuncSetAttribute(layer_kernel, cudaFuncAttributeMaxDynamicSharedMemorySize, SMEM_LAYER);

    const int nodeWarpBlocks = (NN * 32 + 255) / 256;

    // order: profiled capture (launch index 3) = init_combine (E-sized kernel)
    zero_deg_kernel<<<(NN + 255) / 256, 256>>>();                    // 0
    wfuse_kernel<<<1, 128>>>(Wemb, Winit);                           // 1
    z_kernel<<<NN / 64, 128>>>(h, binit);                            // 2
    init_combine_kernel<<<NE / 8, 256>>>(Winit, e, src);             // 3 <- profiled
    deg_count_kernel<<<(NE + 255) / 256, 256>>>(dst);                // 4
    scan_a_kernel<<<NSCAN, SCANB>>>();                               // 5
    scan_b_kernel<<<1, 512>>>();                                     // 6
    scan_c_kernel<<<NSCAN, SCANB>>>();                               // 7
    csr_fill_kernel<<<(NE + 255) / 256, 256>>>(dst);                 // 8

    for (int l = 0; l < 4; ++l) {
        agg_kernel<<<nodeWarpBlocks, 256>>>();
        layer_kernel<<<296, 256, SMEM_LAYER>>>(
            Wlay + (size_t)l * HD * HD, blay + (size_t)l * HD, src);
    }

    wrp_kernel<<<1, HD>>>(Wro, Wpred);
    outinit_kernel<<<(NGB + 255) / 256, 256>>>(out, bpred);
    readout_kernel<<<nodeWarpBlocks, 256>>>(gid, out);
}

// round 13
// speedup vs baseline: 2.6381x; 1.2637x over previous
#include <cuda_runtime.h>
#include <cuda_bf16.h>
#include <mma.h>
#include <cstdint>

using namespace nvcuda;

// D-MPNN on GB300. Round 13: layer GEMMs with cp.async-staged gather
// (no LDG stalls on the critical path) + residual read from the staged
// smem copy (saves 410 MB/layer DRAM). MMA core = R11 (mma.sync,
// register-W, bf16 hi/lo 3-term). Init/CSR/agg/readout = R12.

#define NN 200000
#define NE 800000
#define HD 128
#define NGB 2000
#define SCANB 512
#define NSCAN ((NN + SCANB - 1) / SCANB)

__device__ float g_x[(size_t)NN * HD];          // Z = h@Wf + b
__device__ float g_he[(size_t)NE * HD];
__device__ float g_agg[(size_t)NN * HD];
__device__ float g_wrp[HD];
__device__ float g_wf[28 * HD];
__device__ int g_deg[NN];
__device__ int g_off[NN];
__device__ int g_cursor[NN];
__device__ int g_csr[NE];
__device__ int g_bsum[NSCAN];

__device__ __forceinline__ __nv_bfloat162 pack_hi(float a, float b) {
    return __nv_bfloat162(__float2bfloat16_rn(a), __float2bfloat16_rn(b));
}
__device__ __forceinline__ __nv_bfloat162 pack_lo(float a, float b, __nv_bfloat162 hi) {
    return __nv_bfloat162(__float2bfloat16_rn(a - __bfloat162float(hi.x)),
                          __float2bfloat16_rn(b - __bfloat162float(hi.y)));
}
__device__ __forceinline__ uint32_t b2u(__nv_bfloat162 v) {
    return *reinterpret_cast<uint32_t*>(&v);
}
__device__ __forceinline__ uint32_t smem_u32(const void* p) {
    uint32_t a;
    asm("{ .reg .u64 t; cvta.to.shared.u64 t, %1; cvt.u32.u64 %0, t; }" : "=r"(a) : "l"(p));
    return a;
}
__device__ __forceinline__ void ldsm_x4(uint32_t* r, uint32_t addr) {
    asm volatile("ldmatrix.sync.aligned.m8n8.x4.shared.b16 {%0,%1,%2,%3}, [%4];"
                 : "=r"(r[0]), "=r"(r[1]), "=r"(r[2]), "=r"(r[3]) : "r"(addr));
}
__device__ __forceinline__ void mma16816(float* d, const uint32_t* a, uint32_t b0, uint32_t b1) {
    asm volatile("mma.sync.aligned.m16n8k16.row.col.f32.bf16.bf16.f32 "
                 "{%0,%1,%2,%3},{%4,%5,%6,%7},{%8,%9},{%0,%1,%2,%3};"
                 : "+f"(d[0]), "+f"(d[1]), "+f"(d[2]), "+f"(d[3])
                 : "r"(a[0]), "r"(a[1]), "r"(a[2]), "r"(a[3]), "r"(b0), "r"(b1));
}
__device__ __forceinline__ void cp16(uint32_t smem, const void* g) {
    asm volatile("cp.async.cg.shared.global [%0], [%1], 16;" :: "r"(smem), "l"(g));
}

// ---------------------------------------------------------------- CSR build
__global__ void zero_deg_kernel() {
    int i = blockIdx.x * blockDim.x + threadIdx.x;
    if (i < NN) g_deg[i] = 0;
}
__global__ void deg_count_kernel(const int* __restrict__ dst) {
    int k = blockIdx.x * blockDim.x + threadIdx.x;
    if (k < NE) atomicAdd(&g_deg[dst[k]], 1);
}
__global__ void scan_a_kernel() {
    __shared__ int s[SCANB];
    int t = threadIdx.x;
    int n = blockIdx.x * SCANB + t;
    s[t] = (n < NN) ? g_deg[n] : 0;
    __syncthreads();
    for (int o = SCANB / 2; o > 0; o >>= 1) {
        if (t < o) s[t] += s[t + o];
        __syncthreads();
    }
    if (t == 0) g_bsum[blockIdx.x] = s[0];
}
__global__ void scan_b_kernel() {
    __shared__ int s[512];
    int t = threadIdx.x;
    int v = (t < NSCAN) ? g_bsum[t] : 0;
    s[t] = v;
    __syncthreads();
    for (int o = 1; o < 512; o <<= 1) {
        int x = (t >= o) ? s[t - o] : 0;
        __syncthreads();
        s[t] += x;
        __syncthreads();
    }
    if (t < NSCAN) g_bsum[t] = s[t] - v;
}
__global__ void scan_c_kernel() {
    __shared__ int s[SCANB];
    int t = threadIdx.x;
    int n = blockIdx.x * SCANB + t;
    int val = (n < NN) ? g_deg[n] : 0;
    s[t] = val;
    __syncthreads();
    for (int o = 1; o < SCANB; o <<= 1) {
        int x = (t >= o) ? s[t - o] : 0;
        __syncthreads();
        s[t] += x;
        __syncthreads();
    }
    if (n < NN) {
        int off = g_bsum[blockIdx.x] + s[t] - val;
        g_off[n] = off;
        g_cursor[n] = off;
    }
}
__global__ void csr_fill_kernel(const int* __restrict__ dst) {
    int k = blockIdx.x * blockDim.x + threadIdx.x;
    if (k < NE) {
        int pos = atomicAdd(&g_cursor[dst[k]], 1);
        g_csr[pos] = k;
    }
}

// ---------------------------------------------------------------- Wf = W_emb @ W_init[:128]
__global__ void __launch_bounds__(128) wfuse_kernel(
    const float* __restrict__ Wemb, const float* __restrict__ Winit)
{
    __shared__ float sWe[28 * 128];
    int n = threadIdx.x;
    for (int i = n; i < 28 * 128; i += 128) sWe[i] = Wemb[i];
    __syncthreads();
    float acc[28];
#pragma unroll
    for (int a = 0; a < 28; ++a) acc[a] = 0.f;
    for (int k = 0; k < 128; ++k) {
        float wv = Winit[k * 128 + n];
#pragma unroll
        for (int a = 0; a < 28; ++a) acc[a] += sWe[a * 128 + k] * wv;
    }
#pragma unroll
    for (int a = 0; a < 28; ++a) g_wf[a * 128 + n] = acc[a];
}

// ---------------------------------------------------------------- Z = h @ Wf + b
__global__ void __launch_bounds__(128) z_kernel(
    const float* __restrict__ h, const float* __restrict__ binit)
{
    __shared__ float sh[64 * 28];
    int n0 = blockIdx.x * 64;
    int tid = threadIdx.x;
    for (int idx = tid; idx < 64 * 28; idx += 128)
        sh[idx] = h[(size_t)n0 * 28 + idx];
    __syncthreads();
    float w[28];
#pragma unroll
    for (int i = 0; i < 28; ++i) w[i] = g_wf[i * HD + tid];
    float b = binit[tid];
    for (int n = 0; n < 64; ++n) {
        float acc = b;
#pragma unroll
        for (int i = 0; i < 28; ++i) acc += sh[n * 28 + i] * w[i];
        g_x[(size_t)(n0 + n) * HD + tid] = acc;
    }
}

// ---------------------------------------------------------------- he0 = relu(Z[src] + e@W2)
__global__ void __launch_bounds__(256) init_combine_kernel(
    const float* __restrict__ Winit, const float* __restrict__ eAttr,
    const int* __restrict__ src)
{
    __shared__ float sW2[6 * 128];
    int tid = threadIdx.x;
    for (int i = tid; i < 6 * 128; i += 256) sW2[i] = Winit[128 * 128 + i];
    __syncthreads();

    int k = blockIdx.x * 8 + (tid >> 5);
    int lane = tid & 31;
    int s = __ldg(&src[k]);
    float ev[6];
#pragma unroll
    for (int j = 0; j < 6; ++j) ev[j] = __ldg(&eAttr[(size_t)k * 6 + j]);
    float4 z = *(const float4*)&g_x[(size_t)s * HD + lane * 4];
#pragma unroll
    for (int j = 0; j < 6; ++j) {
        float4 w2 = *(const float4*)&sW2[j * 128 + lane * 4];
        z.x += ev[j] * w2.x; z.y += ev[j] * w2.y;
        z.z += ev[j] * w2.z; z.w += ev[j] * w2.w;
    }
    z.x = fmaxf(z.x, 0.f); z.y = fmaxf(z.y, 0.f);
    z.z = fmaxf(z.z, 0.f); z.w = fmaxf(z.w, 0.f);
    *(float4*)&g_he[(size_t)k * HD + lane * 4] = z;
}

// ---------------------------------------------------------------- layer GEMM
// TE=32, cp.async double-staged raw (he, agg[src]) rows, convert->single A
// bf16 hi/lo buffer, mma.sync with register-B, residual from staged smem.
#define LTE 32
#define LNT (NE / LTE)                  // 25000
#define RAW_LD 132                      // raw row stride in floats
#define RAW_SZ (LTE * RAW_LD)           // floats per raw array
#define LA_SZ (LTE * 136)               // halves per A component
// smem: rawHe[2] | rawAgg[2] | Ahi | Alo
#define SMEM_LAYER (4 * RAW_SZ * 4 + 2 * LA_SZ * 2)   // 67584 + 17408 = 84,992

__global__ void __launch_bounds__(256, 2) layer_kernel(
    const float* __restrict__ W, const float* __restrict__ bias,
    const int* __restrict__ src)
{
    extern __shared__ char sm[];
    float* rawHe = (float*)sm;                        // [2][RAW_SZ]
    float* rawAgg = rawHe + 2 * RAW_SZ;               // [2][RAW_SZ]
    __nv_bfloat16* sAhi = (__nv_bfloat16*)(rawAgg + 2 * RAW_SZ);
    __nv_bfloat16* sAlo = sAhi + LA_SZ;
    uint32_t rawHe_u = smem_u32(rawHe);
    uint32_t rawAgg_u = smem_u32(rawAgg);
    uint32_t sAhi_u = smem_u32(sAhi);
    uint32_t sAlo_u = smem_u32(sAlo);

    int tid = threadIdx.x;
    int w = tid >> 5, l = tid & 31;
    int ncb = w * 16;

    // ---- W into registers (once per block) ----
    uint32_t Bh[8][2][2], Bl[8][2][2];
    {
        int kq = (l & 3) * 2;
        int nn = l >> 2;
#pragma unroll
        for (int kt = 0; kt < 8; ++kt)
#pragma unroll
            for (int j = 0; j < 2; ++j) {
                int n = ncb + j * 8 + nn;
#pragma unroll
                for (int hhf = 0; hhf < 2; ++hhf) {
                    int k0 = kt * 16 + hhf * 8 + kq;
                    float w0 = __ldg(&W[k0 * 128 + n]);
                    float w1 = __ldg(&W[(k0 + 1) * 128 + n]);
                    __nv_bfloat162 hi = pack_hi(w0, w1);
                    Bh[kt][j][hhf] = b2u(hi);
                    Bl[kt][j][hhf] = b2u(pack_lo(w0, w1, hi));
                }
            }
    }
    float bs[2][2];
    {
        int ncl = (l & 3) * 2;
#pragma unroll
        for (int j = 0; j < 2; ++j) {
            bs[j][0] = __ldg(&bias[ncb + j * 8 + ncl]);
            bs[j][1] = __ldg(&bias[ncb + j * 8 + ncl + 1]);
        }
    }

    int quad = l >> 3;
    int arow = (l & 7) + ((quad & 1) ? 8 : 0);
    int acol = (quad >= 2) ? 8 : 0;
    int gr = tid >> 3;                  // staging row 0..31
    int gseg = tid & 7;                 // 16-float segment

    // issue cp.async group for tile t into buffer p (src index pre-loaded)
    auto issue = [&](int t, int p, int sIdx) {
        int e0 = t * LTE;
        const float* gh = &g_he[(size_t)e0 * HD + gr * HD + gseg * 16];
        const float* ga = &g_agg[(size_t)sIdx * HD + gseg * 16];
        uint32_t dh = rawHe_u + (uint32_t)((p * RAW_SZ + gr * RAW_LD + gseg * 16) * 4);
        uint32_t da = rawAgg_u + (uint32_t)((p * RAW_SZ + gr * RAW_LD + gseg * 16) * 4);
#pragma unroll
        for (int c = 0; c < 4; ++c) {
            cp16(dh + 16 * c, gh + 4 * c);
            cp16(da + 16 * c, ga + 4 * c);
        }
        asm volatile("cp.async.commit_group;" ::: "memory");
    };

    int t = blockIdx.x;
    int p = 0;
    int sCur = (t < LNT) ? __ldg(&src[t * LTE + gr]) : 0;
    int sNext = (t + gridDim.x < LNT) ? __ldg(&src[(t + gridDim.x) * LTE + gr]) : 0;
    if (t < LNT) issue(t, 0, sCur);

    for (; t < LNT; ) {
        int tn = t + gridDim.x;
        int e0 = t * LTE;

        if (tn < LNT) {
            issue(tn, p ^ 1, sNext);
            sNext = (tn + gridDim.x < LNT) ? __ldg(&src[(tn + gridDim.x) * LTE + gr]) : 0;
            asm volatile("cp.async.wait_group 1;" ::: "memory");
        } else {
            asm volatile("cp.async.wait_group 0;" ::: "memory");
        }
        __syncthreads();   // raw[p] visible to all

        // ---- convert: m = agg - he(rev) -> A hi/lo (pure smem) ----
        {
            const float* ph = &rawHe[p * RAW_SZ + (gr ^ 1) * RAW_LD + gseg * 16];
            const float* pa = &rawAgg[p * RAW_SZ + gr * RAW_LD + gseg * 16];
            __nv_bfloat162* dh = (__nv_bfloat162*)&sAhi[gr * 136 + gseg * 16];
            __nv_bfloat162* dl = (__nv_bfloat162*)&sAlo[gr * 136 + gseg * 16];
#pragma unroll
            for (int c = 0; c < 4; ++c) {
                float4 av = *(const float4*)(pa + 4 * c);
                float4 hv = *(const float4*)(ph + 4 * c);
                float m0 = av.x - hv.x, m1 = av.y - hv.y;
                float m2 = av.z - hv.z, m3 = av.w - hv.w;
                __nv_bfloat162 h01 = pack_hi(m0, m1);
                __nv_bfloat162 h23 = pack_hi(m2, m3);
                dh[2 * c] = h01; dh[2 * c + 1] = h23;
                dl[2 * c] = pack_lo(m0, m1, h01);
                dl[2 * c + 1] = pack_lo(m2, m3, h23);
            }
        }
        __syncthreads();   // A ready

        // ---- MMA ----
        float acc[2][2][4];
#pragma unroll
        for (int i = 0; i < 2; ++i)
#pragma unroll
            for (int j = 0; j < 2; ++j)
#pragma unroll
                for (int x = 0; x < 4; ++x) acc[i][j][x] = 0.f;

#pragma unroll
        for (int kt = 0; kt < 8; ++kt) {
#pragma unroll
            for (int i = 0; i < 2; ++i) {
                uint32_t ah[4], al[4];
                uint32_t off = (uint32_t)(((i * 16 + arow) * 136 + kt * 16 + acol) * 2);
                ldsm_x4(ah, sAhi_u + off);
                ldsm_x4(al, sAlo_u + off);
#pragma unroll
                for (int j = 0; j < 2; ++j) {
                    mma16816(acc[i][j], ah, Bh[kt][j][0], Bh[kt][j][1]);
                    mma16816(acc[i][j], al, Bh[kt][j][0], Bh[kt][j][1]);
                    mma16816(acc[i][j], ah, Bl[kt][j][0], Bl[kt][j][1]);
                }
            }
        }

        // ---- epilogue: relu(acc+b) + residual (from staged smem) -> g_he ----
        int grow = l >> 2, ncl = (l & 3) * 2;
        const float* rhe = &rawHe[p * RAW_SZ];
#pragma unroll
        for (int i = 0; i < 2; ++i) {
            int rloc = i * 16 + grow;
#pragma unroll
            for (int j = 0; j < 2; ++j) {
                int c = ncb + j * 8 + ncl;
                float h00 = rhe[rloc * RAW_LD + c];
                float h01 = rhe[rloc * RAW_LD + c + 1];
                float h10 = rhe[(rloc + 8) * RAW_LD + c];
                float h11 = rhe[(rloc + 8) * RAW_LD + c + 1];
                float2 o0, o1;
                o0.x = fmaxf(acc[i][j][0] + bs[j][0], 0.f) + h00;
                o0.y = fmaxf(acc[i][j][1] + bs[j][1], 0.f) + h01;
                o1.x = fmaxf(acc[i][j][2] + bs[j][0], 0.f) + h10;
                o1.y = fmaxf(acc[i][j][3] + bs[j][1], 0.f) + h11;
                *(float2*)&g_he[(size_t)(e0 + rloc) * HD + c] = o0;
                *(float2*)&g_he[(size_t)(e0 + rloc + 8) * HD + c] = o1;
            }
        }
        __syncthreads();   // A + raw[p] reads done before reuse
        sCur = sNext;
        t = tn; p ^= 1;
    }
}

// ---------------------------------------------------------------- agg (MLP-4 CSR gather)
__global__ void __launch_bounds__(256) agg_kernel() {
    int node = (blockIdx.x * blockDim.x + threadIdx.x) >> 5;
    int lane = threadIdx.x & 31;
    if (node >= NN) return;
    int start = __ldg(&g_off[node]);
    int d = __ldg(&g_deg[node]);
    float4 acc = make_float4(0.f, 0.f, 0.f, 0.f);
    int j = 0;
    for (; j + 4 <= d; j += 4) {
        int e0 = __ldg(&g_csr[start + j]);
        int e1 = __ldg(&g_csr[start + j + 1]);
        int e2 = __ldg(&g_csr[start + j + 2]);
        int e3 = __ldg(&g_csr[start + j + 3]);
        float4 v0 = ((const float4*)&g_he[(size_t)e0 * HD])[lane];
        float4 v1 = ((const float4*)&g_he[(size_t)e1 * HD])[lane];
        float4 v2 = ((const float4*)&g_he[(size_t)e2 * HD])[lane];
        float4 v3 = ((const float4*)&g_he[(size_t)e3 * HD])[lane];
        acc.x += v0.x + v1.x + v2.x + v3.x;
        acc.y += v0.y + v1.y + v2.y + v3.y;
        acc.z += v0.z + v1.z + v2.z + v3.z;
        acc.w += v0.w + v1.w + v2.w + v3.w;
    }
    for (; j < d; ++j) {
        int e = __ldg(&g_csr[start + j]);
        float4 v = ((const float4*)&g_he[(size_t)e * HD])[lane];
        acc.x += v.x; acc.y += v.y; acc.z += v.z; acc.w += v.w;
    }
    reinterpret_cast<float4*>(&g_agg[(size_t)node * HD])[lane] = acc;
}

// ---------------------------------------------------------------- wrp / outinit / readout
__global__ void wrp_kernel(const float* __restrict__ Wro, const float* __restrict__ Wpred) {
    __shared__ float sp[HD];
    int i = threadIdx.x;
    sp[i] = Wpred[i];
    __syncthreads();
    float a = 0.f;
    for (int j = 0; j < HD; ++j) a += Wro[(size_t)i * HD + j] * sp[j];
    g_wrp[i] = a;
}
__global__ void outinit_kernel(float* __restrict__ out, const float* __restrict__ bpred) {
    int i = blockIdx.x * blockDim.x + threadIdx.x;
    if (i < NGB) out[i] = bpred[0];
}
__global__ void __launch_bounds__(256) readout_kernel(
    const int* __restrict__ gid, float* __restrict__ out)
{
    int node = (blockIdx.x * blockDim.x + threadIdx.x) >> 5;
    int lane = threadIdx.x & 31;
    if (node >= NN) return;
    int start = __ldg(&g_off[node]);
    int d = __ldg(&g_deg[node]);
    float4 acc = make_float4(0.f, 0.f, 0.f, 0.f);
    int j = 0;
    for (; j + 4 <= d; j += 4) {
        int e0 = __ldg(&g_csr[start + j]);
        int e1 = __ldg(&g_csr[start + j + 1]);
        int e2 = __ldg(&g_csr[start + j + 2]);
        int e3 = __ldg(&g_csr[start + j + 3]);
        float4 v0 = ((const float4*)&g_he[(size_t)e0 * HD])[lane];
        float4 v1 = ((const float4*)&g_he[(size_t)e1 * HD])[lane];
        float4 v2 = ((const float4*)&g_he[(size_t)e2 * HD])[lane];
        float4 v3 = ((const float4*)&g_he[(size_t)e3 * HD])[lane];
        acc.x += v0.x + v1.x + v2.x + v3.x;
        acc.y += v0.y + v1.y + v2.y + v3.y;
        acc.z += v0.z + v1.z + v2.z + v3.z;
        acc.w += v0.w + v1.w + v2.w + v3.w;
    }
    for (; j < d; ++j) {
        int e = __ldg(&g_csr[start + j]);
        float4 v = ((const float4*)&g_he[(size_t)e * HD])[lane];
        acc.x += v.x; acc.y += v.y; acc.z += v.z; acc.w += v.w;
    }
    float4 w = reinterpret_cast<const float4*>(g_wrp)[lane];
    float s = acc.x * w.x + acc.y * w.y + acc.z * w.z + acc.w * w.w;
#pragma unroll
    for (int o = 16; o; o >>= 1) s += __shfl_xor_sync(0xFFFFFFFFu, s, o);
    if (lane == 0) atomicAdd(&out[gid[node]], s);
}

// ---------------------------------------------------------------- launch
extern "C" void kernel_launch(void* const* d_in, const int* in_sizes, int n_in,
                              void* d_out, int out_size)
{
    const float* h      = (const float*)d_in[0];
    const float* e      = (const float*)d_in[1];
    const float* Wemb   = (const float*)d_in[2];
    const float* Winit  = (const float*)d_in[3];
    const float* binit  = (const float*)d_in[4];
    const float* Wlay   = (const float*)d_in[5];
    const float* blay   = (const float*)d_in[6];
    const float* Wro    = (const float*)d_in[7];
    const float* Wpred  = (const float*)d_in[8];
    const float* bpred  = (const float*)d_in[9];
    const int*   src    = (const int*)d_in[10];
    const int*   dst    = (const int*)d_in[11];
    const int*   gid    = (const int*)d_in[12];
    float* out = (float*)d_out;

    cudaFuncSetAttribute(layer_kernel, cudaFuncAttributeMaxDynamicSharedMemorySize, SMEM_LAYER);

    const int nodeWarpBlocks = (NN * 32 + 255) / 256;

    zero_deg_kernel<<<(NN + 255) / 256, 256>>>();                    // 0
    wfuse_kernel<<<1, 128>>>(Wemb, Winit);                           // 1
    z_kernel<<<NN / 64, 128>>>(h, binit);                            // 2
    init_combine_kernel<<<NE / 8, 256>>>(Winit, e, src);             // 3 <- profiled
    deg_count_kernel<<<(NE + 255) / 256, 256>>>(dst);                // 4
    scan_a_kernel<<<NSCAN, SCANB>>>();                               // 5
    scan_b_kernel<<<1, 512>>>();                                     // 6
    scan_c_kernel<<<NSCAN, SCANB>>>();                               // 7
    csr_fill_kernel<<<(NE + 255) / 256, 256>>>(dst);                 // 8

    for (int l = 0; l < 4; ++l) {
        agg_kernel<<<nodeWarpBlocks, 256>>>();
        layer_kernel<<<296, 256, SMEM_LAYER>>>(
            Wlay + (size_t)l * HD * HD, blay + (size_t)l * HD, src);
    }

    wrp_kernel<<<1, HD>>>(Wro, Wpred);
    outinit_kernel<<<(NGB + 255) / 256, 256>>>(out, bpred);
    readout_kernel<<<nodeWarpBlocks, 256>>>(gid, out);
}